// round 9
// baseline (speedup 1.0000x reference)
#include <cuda_runtime.h>
#include <cstdint>
#include <cfloat>

#define Bx 8
#define Nn 1024
#define Fdim 256
#define OUTd 256
#define RELd 16
#define Rr 7

#define KC 32
#define SA_STR 36     // agg !TR: sA[n][k] raw
#define ST_STR 136    // agg TR: sAT[k][n] raw
#define SB_STR 36     // permuted rows: 32 data + 4 pad (LDS.128 conflict-free)

#define ABUF 4608                            // max(128*36, 32*136)
#define BBUF 4608                            // 128*36
#define AG_SMEM_FLOATS (2 * (ABUF + BBUF))   // 18432 floats = 73728 B
#define XWBUF 4608                           // 128*36
#define HW_SMEM_FLOATS (4 * XWBUF)           // 18432 floats = 73728 B

#define PSTR (Bx * Nn * OUTd)                // 2,097,152

__device__ float g_Ht[4 * PSTR];             // relations 0,1,3,4 as [o][m'] (tf32, k-paired perm)
__device__ float g_H3[3 * PSTR];             // identities 2,5,6 as [n][o] (tf32)
__device__ float g_P[4 * PSTR];              // partials
__device__ float g_Xr[Bx * Nn * Fdim];       // X rna-rounded, k-paired perm
__device__ float g_Wt[Rr * OUTd * Fdim];     // W transposed [r][o][k'], rna, k-paired perm

__device__ __forceinline__ float to_tf32(float x) {
    float y; asm("cvt.rna.tf32.f32 %0, %1;" : "=f"(y) : "f"(x)); return y;
}
__device__ __forceinline__ float4 round4(float4 v) {
    v.x = to_tf32(v.x); v.y = to_tf32(v.y); v.z = to_tf32(v.z); v.w = to_tf32(v.w);
    return v;
}
__device__ __forceinline__ void mma8(float* c, const uint32_t* a, uint32_t b0, uint32_t b1) {
    asm volatile(
        "mma.sync.aligned.m16n8k8.row.col.f32.tf32.tf32.f32 "
        "{%0,%1,%2,%3}, {%4,%5,%6,%7}, {%8,%9}, {%0,%1,%2,%3};"
        : "+f"(c[0]), "+f"(c[1]), "+f"(c[2]), "+f"(c[3])
        : "r"(a[0]), "r"(a[1]), "r"(a[2]), "r"(a[3]), "r"(b0), "r"(b1));
}
__device__ __forceinline__ uint32_t fbits(const float* p) { return *(const uint32_t*)p; }
__device__ __forceinline__ uint32_t smem_u32(const void* p) {
    uint32_t a;
    asm("{ .reg .u64 t; cvta.to.shared.u64 t, %1; cvt.u32.u64 %0, t; }" : "=r"(a) : "l"(p));
    return a;
}
// pair-permutation within each 32-wide chunk of the contraction index:
// position = (k&3)*8 + (k>>3)*2 + ((k>>2)&1)  (chunk-local)
__device__ __forceinline__ int cperm(int k) {
    int k5 = k & 31;
    return (k & ~31) | ((k5 & 3) << 3) | (((k5 >> 3) & 3) << 1) | ((k5 >> 2) & 1);
}
#define CPA16(dst, src) \
    asm volatile("cp.async.cg.shared.global [%0], [%1], 16;" :: "r"(dst), "l"(src))
#define CPA_COMMIT() asm volatile("cp.async.commit_group;" ::: "memory")
#define CPA_WAIT1()  asm volatile("cp.async.wait_group 1;" ::: "memory")
#define CPA_WAIT0()  asm volatile("cp.async.wait_group 0;" ::: "memory")

// ---------------------------------------------------------------------------
// Prep: g_Xr[m][k'] = rna(X[m][k]) with pair-permuted k
__global__ void xp_kernel(const float* __restrict__ X) {
    int f = blockIdx.x * 256 + threadIdx.x;
    int m = f >> 6, k4 = (f & 63) << 2;
    float4 v = round4(*(const float4*)(X + (size_t)m * Fdim + k4));
    float* dst = g_Xr + (size_t)m * Fdim;
    dst[cperm(k4 + 0)] = v.x; dst[cperm(k4 + 1)] = v.y;
    dst[cperm(k4 + 2)] = v.z; dst[cperm(k4 + 3)] = v.w;
}

// Prep: g_Wt[r][o][k'] = rna(W[r][k][o]) with pair-permuted k
__global__ void wt_prep(const float* __restrict__ W) {
    int f = blockIdx.x * 256 + threadIdx.x;
    int r = f >> 14, u = f & 16383, k4 = (u >> 8) << 2, o = u & 255;
    float* dst = g_Wt + ((size_t)r * OUTd + o) * Fdim;
#pragma unroll
    for (int j = 0; j < 4; j++) {
        float v = to_tf32(W[((size_t)r * (Fdim + RELd) + k4 + j) * OUTd + o]);
        dst[cperm(k4 + j)] = v;
    }
}

// ---------------------------------------------------------------------------
// HW GEMM: tf32( X[m,:]@W[r] + c[r] ) -> g_Ht (r=0,1,3,4) or g_H3 (r=2,5,6)
// Both operands pair-permuted: LDS.128 fragments covering 2 k-steps.
__global__ __launch_bounds__(256, 2) void hw_mma(const float* __restrict__ W,
                                                 const float* __restrict__ We) {
    extern __shared__ float sm[];
    __shared__ float sCv[128];
    float* sA[2] = { sm, sm + XWBUF };
    float* sB[2] = { sm + 2 * XWBUF, sm + 3 * XWBUF };
    const uint32_t saU[2] = { smem_u32(sA[0]), smem_u32(sA[1]) };
    const uint32_t sbU[2] = { smem_u32(sB[0]), smem_u32(sB[1]) };

    const int tid = threadIdx.x, lane = tid & 31, wid = tid >> 5;
    const int warp_m = (wid & 3) * 32, warp_n = (wid >> 2) * 64;
    const int grp = lane >> 2, tg = lane & 3;

    const int r  = blockIdx.x >> 1;
    const int o0 = (blockIdx.x & 1) * 128;
    const int m0 = blockIdx.y * 128;

    if (tid < 128) {
        float s = 0.f;
#pragma unroll
        for (int d = 0; d < RELd; d++)
            s += We[r * RELd + d] * W[((size_t)r * (Fdim + RELd) + Fdim + d) * OUTd + o0 + tid];
        sCv[tid] = s;
    }

    const float* Xb = g_Xr + (size_t)m0 * Fdim;
    const float* Wt = g_Wt + ((size_t)r * OUTd + o0) * Fdim;

    float acc[2][8][4];
#pragma unroll
    for (int mt = 0; mt < 2; mt++)
#pragma unroll
        for (int nt = 0; nt < 8; nt++)
#pragma unroll
            for (int j = 0; j < 4; j++) acc[mt][nt][j] = 0.f;

    auto loadc = [&](int k0, int s) {
#pragma unroll
        for (int i = 0; i < 4; i++) {
            int f = tid + i * 256, row = f >> 3, s4 = (f & 7) << 2;
            CPA16(saU[s] + (row * SB_STR + s4) * 4, Xb + (size_t)row * Fdim + k0 + s4);
            CPA16(sbU[s] + (row * SB_STR + s4) * 4, Wt + (size_t)row * Fdim + k0 + s4);
        }
    };

    const int NC = Fdim / KC;  // 8
    loadc(0, 0);  CPA_COMMIT();
    loadc(KC, 1); CPA_COMMIT();

    for (int c = 0; c < NC; c++) {
        const int buf = c & 1;
        if (c + 1 < NC) CPA_WAIT1(); else CPA_WAIT0();
        __syncthreads();

        const float* cA = sA[buf] + tg * 8;
        const float* cB = sB[buf] + (warp_n + grp) * SB_STR + tg * 8;
#pragma unroll
        for (int j = 0; j < 2; j++) {        // ks-pairs: (0,1) and (2,3)
            const int jo = j * 4;
            // A rows: one LDS.128 each covers both ks of the pair
            float4 va0 = *(const float4*)(cA + (warp_m + grp) * SB_STR + jo);
            float4 va1 = *(const float4*)(cA + (warp_m + 8 + grp) * SB_STR + jo);
            float4 va2 = *(const float4*)(cA + (warp_m + 16 + grp) * SB_STR + jo);
            float4 va3 = *(const float4*)(cA + (warp_m + 24 + grp) * SB_STR + jo);
            uint32_t f00[4] = { fbits(&va0.x), fbits(&va1.x), fbits(&va0.y), fbits(&va1.y) };
            uint32_t f01[4] = { fbits(&va2.x), fbits(&va3.x), fbits(&va2.y), fbits(&va3.y) };
            uint32_t f10[4] = { fbits(&va0.z), fbits(&va1.z), fbits(&va0.w), fbits(&va1.w) };
            uint32_t f11[4] = { fbits(&va2.z), fbits(&va3.z), fbits(&va2.w), fbits(&va3.w) };
#pragma unroll
            for (int nt = 0; nt < 8; nt++) {
                const float4 bv = *(const float4*)(cB + nt * 8 * SB_STR + jo);
                mma8(acc[0][nt], f00, fbits(&bv.x), fbits(&bv.y));
                mma8(acc[1][nt], f01, fbits(&bv.x), fbits(&bv.y));
                mma8(acc[0][nt], f10, fbits(&bv.z), fbits(&bv.w));
                mma8(acc[1][nt], f11, fbits(&bv.z), fbits(&bv.w));
            }
        }
        if (c + 2 < NC) {
            __syncthreads();
            loadc((c + 2) * KC, buf);
            CPA_COMMIT();
        }
    }

    const bool isId = (r == 2 || r == 5 || r == 6);
    if (isId) {
        const int zi = (r == 2) ? 0 : (r == 5) ? 1 : 2;
#pragma unroll
        for (int mt = 0; mt < 2; mt++) {
#pragma unroll
            for (int nt = 0; nt < 8; nt++) {
                const int ol = warp_n + nt * 8 + 2 * tg;
                const float2 cv = *(const float2*)(sCv + ol);
                const int o = o0 + ol;
                int mg = m0 + warp_m + mt * 16 + grp;
                int b = mg >> 10, n = mg & 1023;
                float* dst = g_H3 + (((size_t)(zi * Bx + b) * Nn + n) * OUTd) + o;
                *(float2*)dst = make_float2(to_tf32(acc[mt][nt][0] + cv.x),
                                            to_tf32(acc[mt][nt][1] + cv.y));
                mg += 8; b = mg >> 10; n = mg & 1023;
                dst = g_H3 + (((size_t)(zi * Bx + b) * Nn + n) * OUTd) + o;
                *(float2*)dst = make_float2(to_tf32(acc[mt][nt][2] + cv.x),
                                            to_tf32(acc[mt][nt][3] + cv.y));
            }
        }
    } else {
        const int ti = (r < 2) ? r : r - 1;
#pragma unroll
        for (int mt = 0; mt < 2; mt++) {
#pragma unroll
            for (int nt = 0; nt < 8; nt++) {
                const int ol = warp_n + nt * 8 + 2 * tg;
                const float2 cv = *(const float2*)(sCv + ol);
                const int o = o0 + ol;
                int mg = m0 + warp_m + mt * 16 + grp;
                {
                    int b = mg >> 10, n = mg & 1023, np = cperm(n);
                    float* base = g_Ht + ((size_t)(ti * Bx + b) * OUTd + o) * Nn;
                    base[np]      = to_tf32(acc[mt][nt][0] + cv.x);
                    base[Nn + np] = to_tf32(acc[mt][nt][1] + cv.y);
                }
                mg += 8;
                {
                    int b = mg >> 10, n = mg & 1023, np = cperm(n);
                    float* base = g_Ht + ((size_t)(ti * Bx + b) * OUTd + o) * Nn;
                    base[np]      = to_tf32(acc[mt][nt][2] + cv.x);
                    base[Nn + np] = to_tf32(acc[mt][nt][3] + cv.y);
                }
            }
        }
    }
}

// ---------------------------------------------------------------------------
// Aggregation: CTA tile 128(n) x 128(o), 8 warps, B frags via LDS.128 pairs.
template <bool TR>
__device__ __forceinline__ void agg_load(uint32_t sa, uint32_t sb,
                                         const float* Ab, const float* Hb,
                                         int n0, int k0, int tid) {
#pragma unroll
    for (int i = 0; i < 4; i++) {
        int f = tid + i * 256;
        if (!TR) {
            int m = f >> 3, k4 = (f & 7) << 2;
            CPA16(sa + (m * SA_STR + k4) * 4, Ab + (size_t)(n0 + m) * Nn + k0 + k4);
        } else {
            int kk = f >> 5, n4 = (f & 31) << 2;
            CPA16(sa + (kk * ST_STR + n4) * 4, Ab + (size_t)(k0 + kk) * Nn + n0 + n4);
        }
        int o = f >> 3, s4 = (f & 7) << 2;
        CPA16(sb + (o * SB_STR + s4) * 4, Hb + (size_t)o * Nn + k0 + s4);
    }
}

template <bool TR>
__device__ __forceinline__ void agg_body(const float* Ab, const float* Hb,
                                         float* Pout, int n0, int o0) {
    extern __shared__ float sm[];
    float* sA[2] = { sm, sm + ABUF };
    float* sB[2] = { sm + 2 * ABUF, sm + 2 * ABUF + BBUF };
    const uint32_t saU[2] = { smem_u32(sA[0]), smem_u32(sA[1]) };
    const uint32_t sbU[2] = { smem_u32(sB[0]), smem_u32(sB[1]) };

    const int tid = threadIdx.x, lane = tid & 31, wid = tid >> 5;
    const int warp_m = (wid & 3) * 32, warp_n = (wid >> 2) * 64;
    const int grp = lane >> 2, tg = lane & 3;

    float acc[2][8][4];
#pragma unroll
    for (int mt = 0; mt < 2; mt++)
#pragma unroll
        for (int nt = 0; nt < 8; nt++)
#pragma unroll
            for (int j = 0; j < 4; j++) acc[mt][nt][j] = 0.f;

    const int NC = Nn / KC;  // 32
    agg_load<TR>(saU[0], sbU[0], Ab, Hb, n0, 0, tid);
    CPA_COMMIT();
    agg_load<TR>(saU[1], sbU[1], Ab, Hb, n0, KC, tid);
    CPA_COMMIT();

    for (int c = 0; c < NC; c++) {
        const int buf = c & 1;
        if (c + 1 < NC) CPA_WAIT1(); else CPA_WAIT0();
        __syncthreads();

        const float* cA = sA[buf];
        const float* cB = sB[buf] + (warp_n + grp) * SB_STR + tg * 8;
#pragma unroll
        for (int j = 0; j < 2; j++) {        // ks-pairs
            const int jo = j * 4;
            uint32_t afr[2][2][4];           // [ks-in-pair][mt][4]
#pragma unroll
            for (int kk = 0; kk < 2; kk++) {
                const int cc = (j * 2 + kk) * 8 + tg;
#pragma unroll
                for (int mt = 0; mt < 2; mt++) {
                    int rr = warp_m + mt * 16 + grp;
                    if (!TR) {
                        afr[kk][mt][0] = fbits(cA + rr * SA_STR + cc);
                        afr[kk][mt][1] = fbits(cA + (rr + 8) * SA_STR + cc);
                        afr[kk][mt][2] = fbits(cA + rr * SA_STR + cc + 4);
                        afr[kk][mt][3] = fbits(cA + (rr + 8) * SA_STR + cc + 4);
                    } else {
                        afr[kk][mt][0] = fbits(cA + cc * ST_STR + rr);
                        afr[kk][mt][1] = fbits(cA + cc * ST_STR + rr + 8);
                        afr[kk][mt][2] = fbits(cA + (cc + 4) * ST_STR + rr);
                        afr[kk][mt][3] = fbits(cA + (cc + 4) * ST_STR + rr + 8);
                    }
                }
            }
#pragma unroll
            for (int nt = 0; nt < 8; nt++) {
                const float4 bv = *(const float4*)(cB + nt * 8 * SB_STR + jo);
                mma8(acc[0][nt], afr[0][0], fbits(&bv.x), fbits(&bv.y));
                mma8(acc[1][nt], afr[0][1], fbits(&bv.x), fbits(&bv.y));
                mma8(acc[0][nt], afr[1][0], fbits(&bv.z), fbits(&bv.w));
                mma8(acc[1][nt], afr[1][1], fbits(&bv.z), fbits(&bv.w));
            }
        }
        if (c + 2 < NC) {
            __syncthreads();
            agg_load<TR>(saU[buf], sbU[buf], Ab, Hb, n0, (c + 2) * KC, tid);
            CPA_COMMIT();
        }
    }

#pragma unroll
    for (int mt = 0; mt < 2; mt++) {
#pragma unroll
        for (int nt = 0; nt < 8; nt++) {
            const int o = o0 + warp_n + nt * 8 + 2 * tg;
#pragma unroll
            for (int h = 0; h < 2; h++) {
                const int n = n0 + warp_m + mt * 16 + grp + h * 8;
                *(float2*)(Pout + (size_t)n * OUTd + o) =
                    make_float2(acc[mt][nt][2 * h], acc[mt][nt][2 * h + 1]);
            }
        }
    }
}

__global__ __launch_bounds__(256, 2) void agg_pass(const float* __restrict__ A1,
                                                   const float* __restrict__ A2) {
    const int o0 = blockIdx.x * 128;
    const int n0 = blockIdx.y * 128;
    const int z  = blockIdx.z;
    const int b  = z & 7;
    const int p  = z >> 3;                   // 0:A1@H0 1:A2@H1 2:A1t@H3 3:A2t@H4
    const int q  = p & 1;
    const float* Ab = (q == 0 ? A1 : A2) + (size_t)b * Nn * Nn;
    const float* Hb = g_Ht + ((size_t)(p * Bx + b) * OUTd + o0) * Nn;
    float* Pout = g_P + (size_t)p * PSTR + ((size_t)b * Nn) * OUTd;

    if (p < 2) agg_body<false>(Ab, Hb, Pout, n0, o0);
    else       agg_body<true >(Ab, Hb, Pout, n0, o0);
}

// ---------------------------------------------------------------------------
__global__ __launch_bounds__(256) void fold_kernel(const float* __restrict__ bias,
                                                   float* __restrict__ out) {
    const int idx = (blockIdx.x * 256 + threadIdx.x) * 4;
    float4 v = *(const float4*)(g_P + idx);
    float4 t;
#pragma unroll
    for (int p = 1; p < 4; p++) {
        t = *(const float4*)(g_P + (size_t)p * PSTR + idx);
        v.x = fmaxf(v.x, t.x); v.y = fmaxf(v.y, t.y);
        v.z = fmaxf(v.z, t.z); v.w = fmaxf(v.w, t.w);
    }
#pragma unroll
    for (int zi = 0; zi < 3; zi++) {
        t = *(const float4*)(g_H3 + (size_t)zi * PSTR + idx);
        v.x = fmaxf(v.x, t.x); v.y = fmaxf(v.y, t.y);
        v.z = fmaxf(v.z, t.z); v.w = fmaxf(v.w, t.w);
    }
    const int bi = idx & (Nn * OUTd - 1);
    t = *(const float4*)(bias + bi);
    v.x += t.x; v.y += t.y; v.z += t.z; v.w += t.w;
    *(float4*)(out + idx) = v;
}

// ---------------------------------------------------------------------------
extern "C" void kernel_launch(void* const* d_in, const int* in_sizes, int n_in,
                              void* d_out, int out_size) {
    const float* X    = (const float*)d_in[0];
    const float* A1   = (const float*)d_in[1];
    const float* A2   = (const float*)d_in[2];
    const float* W    = (const float*)d_in[3];
    const float* We   = (const float*)d_in[4];
    const float* bias = (const float*)d_in[5];
    float* out = (float*)d_out;

    const int hw_smem = HW_SMEM_FLOATS * sizeof(float);
    const int ag_smem = AG_SMEM_FLOATS * sizeof(float);
    cudaFuncSetAttribute(hw_mma,   cudaFuncAttributeMaxDynamicSharedMemorySize, hw_smem);
    cudaFuncSetAttribute(agg_pass, cudaFuncAttributeMaxDynamicSharedMemorySize, ag_smem);

    xp_kernel<<<2048, 256>>>(X);
    wt_prep<<<448, 256>>>(W);

    dim3 gHW(14, 64);
    hw_mma<<<gHW, 256, hw_smem>>>(W, We);

    dim3 gAgg(2, 8, 32);
    agg_pass<<<gAgg, 256, ag_smem>>>(A1, A2);

    fold_kernel<<<(Bx * Nn * OUTd) / 1024, 256>>>(bias, out);
}

// round 10
// speedup vs baseline: 1.1804x; 1.1804x over previous
#include <cuda_runtime.h>
#include <cstdint>
#include <cfloat>

#define Bx 8
#define Nn 1024
#define Fdim 256
#define OUTd 256
#define RELd 16
#define Rr 7

#define KC 32
#define SA_STR 36     // agg !TR: sA[n][k], scalar frags conflict-free
#define ST_STR 136    // agg TR: sAT[k][n]
#define SB_STR 40     // k'-permuted rows: 32 data + 8 pad (conflict-free LDS.64)

#define ABUF 4608                            // max(128*36, 32*136)
#define BBUF_AG 5120                         // 128*40
#define AG_SMEM_FLOATS (2 * (ABUF + BBUF_AG))    // 19456 floats = 77824 B
#define XWBUF 5120                           // 128*40
#define HW_SMEM_FLOATS (4 * XWBUF)           // 20480 floats = 81920 B

#define PSTR (Bx * Nn * OUTd)                // 2,097,152

__device__ float g_Ht[4 * PSTR];             // relations 0,1,3,4 as [o][m'] (tf32)
__device__ float g_H3[3 * PSTR];             // identities 2,5,6 as [n][o] (tf32)
__device__ float g_P[4 * PSTR];              // partials
__device__ float g_Xr[Bx * Nn * Fdim];       // X rna-rounded, k-permuted
__device__ float g_Wt[Rr * OUTd * Fdim];     // W transposed [r][o][k'], rna, k-permuted

__device__ __forceinline__ float to_tf32(float x) {
    float y; asm("cvt.rna.tf32.f32 %0, %1;" : "=f"(y) : "f"(x)); return y;
}
__device__ __forceinline__ float4 round4(float4 v) {
    v.x = to_tf32(v.x); v.y = to_tf32(v.y); v.z = to_tf32(v.z); v.w = to_tf32(v.w);
    return v;
}
__device__ __forceinline__ void mma8(float* c, const uint32_t* a, uint32_t b0, uint32_t b1) {
    asm volatile(
        "mma.sync.aligned.m16n8k8.row.col.f32.tf32.tf32.f32 "
        "{%0,%1,%2,%3}, {%4,%5,%6,%7}, {%8,%9}, {%0,%1,%2,%3};"
        : "+f"(c[0]), "+f"(c[1]), "+f"(c[2]), "+f"(c[3])
        : "r"(a[0]), "r"(a[1]), "r"(a[2]), "r"(a[3]), "r"(b0), "r"(b1));
}
__device__ __forceinline__ uint32_t fbits(const float* p) { return *(const uint32_t*)p; }
__device__ __forceinline__ uint32_t smem_u32(const void* p) {
    uint32_t a;
    asm("{ .reg .u64 t; cvta.to.shared.u64 t, %1; cvt.u32.u64 %0, t; }" : "=r"(a) : "l"(p));
    return a;
}
// octet permutation of contraction index: pairs (k, k+4) become adjacent
__device__ __forceinline__ int operm(int n) {
    return (n & ~7) | (((n & 3) << 1) | ((n >> 2) & 1));
}
#define CPA16(dst, src) \
    asm volatile("cp.async.cg.shared.global [%0], [%1], 16;" :: "r"(dst), "l"(src))
#define CPA_COMMIT() asm volatile("cp.async.commit_group;" ::: "memory")
#define CPA_WAIT0()  asm volatile("cp.async.wait_group 0;" ::: "memory")

// ---------------------------------------------------------------------------
// Prep: g_Xr[m][k'] = rna(X[m][k])
__global__ void xp_kernel(const float* __restrict__ X) {
    int f = blockIdx.x * 256 + threadIdx.x;
    int m = f >> 6, k4 = (f & 63) << 2;
    float4 v = round4(*(const float4*)(X + (size_t)m * Fdim + k4));
    float* dst = g_Xr + (size_t)m * Fdim;
    dst[operm(k4 + 0)] = v.x; dst[operm(k4 + 1)] = v.y;
    dst[operm(k4 + 2)] = v.z; dst[operm(k4 + 3)] = v.w;
}

// Prep: g_Wt[r][o][k'] = rna(W[r][k][o])
__global__ void wt_prep(const float* __restrict__ W) {
    int f = blockIdx.x * 256 + threadIdx.x;
    int r = f >> 14, u = f & 16383, k4 = (u >> 8) << 2, o = u & 255;
    float* dst = g_Wt + ((size_t)r * OUTd + o) * Fdim;
#pragma unroll
    for (int j = 0; j < 4; j++) {
        float v = to_tf32(W[((size_t)r * (Fdim + RELd) + k4 + j) * OUTd + o]);
        dst[operm(k4 + j)] = v;
    }
}

// ---------------------------------------------------------------------------
// HW GEMM: tf32( X[m,:]@W[r] + c[r] ) -> g_Ht (r=0,1,3,4) or g_H3 (r=2,5,6)
// Single-barrier pipelined loop.
__global__ __launch_bounds__(256, 2) void hw_mma(const float* __restrict__ W,
                                                 const float* __restrict__ We) {
    extern __shared__ float sm[];
    __shared__ float sCv[128];
    float* sA[2] = { sm, sm + XWBUF };
    float* sB[2] = { sm + 2 * XWBUF, sm + 3 * XWBUF };
    const uint32_t saU[2] = { smem_u32(sA[0]), smem_u32(sA[1]) };
    const uint32_t sbU[2] = { smem_u32(sB[0]), smem_u32(sB[1]) };

    const int tid = threadIdx.x, lane = tid & 31, wid = tid >> 5;
    const int warp_m = (wid & 3) * 32, warp_n = (wid >> 2) * 64;
    const int grp = lane >> 2, tg = lane & 3;

    const int r  = blockIdx.x >> 1;
    const int o0 = (blockIdx.x & 1) * 128;
    const int m0 = blockIdx.y * 128;

    if (tid < 128) {
        float s = 0.f;
#pragma unroll
        for (int d = 0; d < RELd; d++)
            s += We[r * RELd + d] * W[((size_t)r * (Fdim + RELd) + Fdim + d) * OUTd + o0 + tid];
        sCv[tid] = s;
    }

    const float* Xb = g_Xr + (size_t)m0 * Fdim;
    const float* Wt = g_Wt + ((size_t)r * OUTd + o0) * Fdim;

    float acc[2][8][4];
#pragma unroll
    for (int mt = 0; mt < 2; mt++)
#pragma unroll
        for (int nt = 0; nt < 8; nt++)
#pragma unroll
            for (int j = 0; j < 4; j++) acc[mt][nt][j] = 0.f;

    auto loadc = [&](int k0, int s) {
#pragma unroll
        for (int i = 0; i < 4; i++) {
            int f = tid + i * 256, row = f >> 3, s4 = (f & 7) << 2;
            CPA16(saU[s] + (row * SB_STR + s4) * 4, Xb + (size_t)row * Fdim + k0 + s4);
            CPA16(sbU[s] + (row * SB_STR + s4) * 4, Wt + (size_t)row * Fdim + k0 + s4);
        }
    };

    const int NC = Fdim / KC;  // 8
    loadc(0, 0); CPA_COMMIT();

    for (int c = 0; c < NC; c++) {
        const int buf = c & 1;
        CPA_WAIT0();                 // per-warp: chunk c landed
        __syncthreads();             // visibility + buffer (c+1)&1 free
        if (c + 1 < NC) { loadc((c + 1) * KC, buf ^ 1); CPA_COMMIT(); }

        const float* cA = sA[buf] + 2 * tg;
        const float* cB = sB[buf] + (warp_n + grp) * SB_STR + 2 * tg;
#pragma unroll
        for (int ks = 0; ks < 4; ks++) {
            const int kp = ks * 8;
            float2 va0 = *(const float2*)(cA + (warp_m + grp) * SB_STR + kp);
            float2 vb0 = *(const float2*)(cA + (warp_m + 8 + grp) * SB_STR + kp);
            float2 va1 = *(const float2*)(cA + (warp_m + 16 + grp) * SB_STR + kp);
            float2 vb1 = *(const float2*)(cA + (warp_m + 24 + grp) * SB_STR + kp);
            uint32_t a0[4] = { fbits(&va0.x), fbits(&vb0.x), fbits(&va0.y), fbits(&vb0.y) };
            uint32_t a1[4] = { fbits(&va1.x), fbits(&vb1.x), fbits(&va1.y), fbits(&vb1.y) };
#pragma unroll
            for (int nt = 0; nt < 8; nt++) {
                const float2 bv = *(const float2*)(cB + nt * 8 * SB_STR + kp);
                mma8(acc[0][nt], a0, fbits(&bv.x), fbits(&bv.y));
                mma8(acc[1][nt], a1, fbits(&bv.x), fbits(&bv.y));
            }
        }
    }

    const bool isId = (r == 2 || r == 5 || r == 6);
    if (isId) {
        const int zi = (r == 2) ? 0 : (r == 5) ? 1 : 2;
#pragma unroll
        for (int mt = 0; mt < 2; mt++) {
#pragma unroll
            for (int nt = 0; nt < 8; nt++) {
                const int ol = warp_n + nt * 8 + 2 * tg;
                const float2 cv = *(const float2*)(sCv + ol);
                const int o = o0 + ol;
                int mg = m0 + warp_m + mt * 16 + grp;
                int b = mg >> 10, n = mg & 1023;
                float* dst = g_H3 + (((size_t)(zi * Bx + b) * Nn + n) * OUTd) + o;
                *(float2*)dst = make_float2(to_tf32(acc[mt][nt][0] + cv.x),
                                            to_tf32(acc[mt][nt][1] + cv.y));
                mg += 8; b = mg >> 10; n = mg & 1023;
                dst = g_H3 + (((size_t)(zi * Bx + b) * Nn + n) * OUTd) + o;
                *(float2*)dst = make_float2(to_tf32(acc[mt][nt][2] + cv.x),
                                            to_tf32(acc[mt][nt][3] + cv.y));
            }
        }
    } else {
        const int ti = (r < 2) ? r : r - 1;
#pragma unroll
        for (int mt = 0; mt < 2; mt++) {
#pragma unroll
            for (int nt = 0; nt < 8; nt++) {
                const int ol = warp_n + nt * 8 + 2 * tg;
                const float2 cv = *(const float2*)(sCv + ol);
                const int o = o0 + ol;
                int mg = m0 + warp_m + mt * 16 + grp;
                {
                    int b = mg >> 10, n = mg & 1023, np = operm(n);
                    float* base = g_Ht + ((size_t)(ti * Bx + b) * OUTd + o) * Nn;
                    base[np]      = to_tf32(acc[mt][nt][0] + cv.x);
                    base[Nn + np] = to_tf32(acc[mt][nt][1] + cv.y);
                }
                mg += 8;
                {
                    int b = mg >> 10, n = mg & 1023, np = operm(n);
                    float* base = g_Ht + ((size_t)(ti * Bx + b) * OUTd + o) * Nn;
                    base[np]      = to_tf32(acc[mt][nt][2] + cv.x);
                    base[Nn + np] = to_tf32(acc[mt][nt][3] + cv.y);
                }
            }
        }
    }
}

// ---------------------------------------------------------------------------
// Aggregation: CTA tile 128(n) x 128(o), single-barrier pipelined loop.
template <bool TR>
__device__ __forceinline__ void agg_load(uint32_t sa, uint32_t sb,
                                         const float* Ab, const float* Hb,
                                         int n0, int k0, int tid) {
#pragma unroll
    for (int i = 0; i < 4; i++) {
        int f = tid + i * 256;
        if (!TR) {
            int m = f >> 3, k4 = (f & 7) << 2;
            CPA16(sa + (m * SA_STR + k4) * 4, Ab + (size_t)(n0 + m) * Nn + k0 + k4);
        } else {
            int kk = f >> 5, n4 = (f & 31) << 2;
            CPA16(sa + (kk * ST_STR + n4) * 4, Ab + (size_t)(k0 + kk) * Nn + n0 + n4);
        }
        int o = f >> 3, s4 = (f & 7) << 2;
        CPA16(sb + (o * SB_STR + s4) * 4, Hb + (size_t)o * Nn + k0 + s4);
    }
}

template <bool TR>
__device__ __forceinline__ void agg_body(const float* Ab, const float* Hb,
                                         float* Pout, int n0, int o0) {
    extern __shared__ float sm[];
    float* sA[2] = { sm, sm + ABUF };
    float* sB[2] = { sm + 2 * ABUF, sm + 2 * ABUF + BBUF_AG };
    const uint32_t saU[2] = { smem_u32(sA[0]), smem_u32(sA[1]) };
    const uint32_t sbU[2] = { smem_u32(sB[0]), smem_u32(sB[1]) };

    const int tid = threadIdx.x, lane = tid & 31, wid = tid >> 5;
    const int warp_m = (wid & 3) * 32, warp_n = (wid >> 2) * 64;
    const int grp = lane >> 2, tg = lane & 3;

    float acc[2][8][4];
#pragma unroll
    for (int mt = 0; mt < 2; mt++)
#pragma unroll
        for (int nt = 0; nt < 8; nt++)
#pragma unroll
            for (int j = 0; j < 4; j++) acc[mt][nt][j] = 0.f;

    const int NC = Nn / KC;  // 32
    agg_load<TR>(saU[0], sbU[0], Ab, Hb, n0, 0, tid);
    CPA_COMMIT();

    for (int c = 0; c < NC; c++) {
        const int buf = c & 1;
        CPA_WAIT0();
        __syncthreads();
        if (c + 1 < NC) {
            agg_load<TR>(saU[buf ^ 1], sbU[buf ^ 1], Ab, Hb, n0, (c + 1) * KC, tid);
            CPA_COMMIT();
        }

        const float* cA = sA[buf];
        const float* cB = sB[buf] + (warp_n + grp) * SB_STR + 2 * tg;
#pragma unroll
        for (int ks = 0; ks < 4; ks++) {
            const int k = ks * 8;
            uint32_t afr[2][4];
#pragma unroll
            for (int mt = 0; mt < 2; mt++) {
                int rr = warp_m + mt * 16 + grp, cc = k + tg;
                if (!TR) {
                    afr[mt][0] = fbits(cA + rr * SA_STR + cc);
                    afr[mt][1] = fbits(cA + (rr + 8) * SA_STR + cc);
                    afr[mt][2] = fbits(cA + rr * SA_STR + cc + 4);
                    afr[mt][3] = fbits(cA + (rr + 8) * SA_STR + cc + 4);
                } else {
                    afr[mt][0] = fbits(cA + cc * ST_STR + rr);
                    afr[mt][1] = fbits(cA + cc * ST_STR + rr + 8);
                    afr[mt][2] = fbits(cA + (cc + 4) * ST_STR + rr);
                    afr[mt][3] = fbits(cA + (cc + 4) * ST_STR + rr + 8);
                }
            }
#pragma unroll
            for (int nt = 0; nt < 8; nt++) {
                const float2 bv = *(const float2*)(cB + nt * 8 * SB_STR + k);
                uint32_t b0 = fbits(&bv.x), b1 = fbits(&bv.y);
                mma8(acc[0][nt], afr[0], b0, b1);
                mma8(acc[1][nt], afr[1], b0, b1);
            }
        }
    }

#pragma unroll
    for (int mt = 0; mt < 2; mt++) {
#pragma unroll
        for (int nt = 0; nt < 8; nt++) {
            const int o = o0 + warp_n + nt * 8 + 2 * tg;
#pragma unroll
            for (int h = 0; h < 2; h++) {
                const int n = n0 + warp_m + mt * 16 + grp + h * 8;
                *(float2*)(Pout + (size_t)n * OUTd + o) =
                    make_float2(acc[mt][nt][2 * h], acc[mt][nt][2 * h + 1]);
            }
        }
    }
}

__global__ __launch_bounds__(256, 2) void agg_pass(const float* __restrict__ A1,
                                                   const float* __restrict__ A2) {
    const int o0 = blockIdx.x * 128;
    const int n0 = blockIdx.y * 128;
    const int z  = blockIdx.z;
    const int b  = z & 7;
    const int p  = z >> 3;                   // 0:A1@H0 1:A2@H1 2:A1t@H3 3:A2t@H4
    const int q  = p & 1;
    const float* Ab = (q == 0 ? A1 : A2) + (size_t)b * Nn * Nn;
    const float* Hb = g_Ht + ((size_t)(p * Bx + b) * OUTd + o0) * Nn;
    float* Pout = g_P + (size_t)p * PSTR + ((size_t)b * Nn) * OUTd;

    if (p < 2) agg_body<false>(Ab, Hb, Pout, n0, o0);
    else       agg_body<true >(Ab, Hb, Pout, n0, o0);
}

// ---------------------------------------------------------------------------
__global__ __launch_bounds__(256) void fold_kernel(const float* __restrict__ bias,
                                                   float* __restrict__ out) {
    const int idx = (blockIdx.x * 256 + threadIdx.x) * 4;
    float4 v = *(const float4*)(g_P + idx);
    float4 t;
#pragma unroll
    for (int p = 1; p < 4; p++) {
        t = *(const float4*)(g_P + (size_t)p * PSTR + idx);
        v.x = fmaxf(v.x, t.x); v.y = fmaxf(v.y, t.y);
        v.z = fmaxf(v.z, t.z); v.w = fmaxf(v.w, t.w);
    }
#pragma unroll
    for (int zi = 0; zi < 3; zi++) {
        t = *(const float4*)(g_H3 + (size_t)zi * PSTR + idx);
        v.x = fmaxf(v.x, t.x); v.y = fmaxf(v.y, t.y);
        v.z = fmaxf(v.z, t.z); v.w = fmaxf(v.w, t.w);
    }
    const int bi = idx & (Nn * OUTd - 1);
    t = *(const float4*)(bias + bi);
    v.x += t.x; v.y += t.y; v.z += t.z; v.w += t.w;
    *(float4*)(out + idx) = v;
}

// ---------------------------------------------------------------------------
extern "C" void kernel_launch(void* const* d_in, const int* in_sizes, int n_in,
                              void* d_out, int out_size) {
    const float* X    = (const float*)d_in[0];
    const float* A1   = (const float*)d_in[1];
    const float* A2   = (const float*)d_in[2];
    const float* W    = (const float*)d_in[3];
    const float* We   = (const float*)d_in[4];
    const float* bias = (const float*)d_in[5];
    float* out = (float*)d_out;

    const int hw_smem = HW_SMEM_FLOATS * sizeof(float);
    const int ag_smem = AG_SMEM_FLOATS * sizeof(float);
    cudaFuncSetAttribute(hw_mma,   cudaFuncAttributeMaxDynamicSharedMemorySize, hw_smem);
    cudaFuncSetAttribute(agg_pass, cudaFuncAttributeMaxDynamicSharedMemorySize, ag_smem);

    xp_kernel<<<2048, 256>>>(X);
    wt_prep<<<448, 256>>>(W);

    dim3 gHW(14, 64);
    hw_mma<<<gHW, 256, hw_smem>>>(W, We);

    dim3 gAgg(2, 8, 32);
    agg_pass<<<gAgg, 256, ag_smem>>>(A1, A2);

    fold_kernel<<<(Bx * Nn * OUTd) / 1024, 256>>>(bias, out);
}

// round 11
// speedup vs baseline: 1.3196x; 1.1179x over previous
#include <cuda_runtime.h>
#include <cuda_fp16.h>
#include <cstdint>

#define Bx 8
#define Nn 1024
#define Fdim 256
#define OUTd 256
#define RELd 16
#define Rr 7

// ---- hw (tf32) params (unchanged from R10) ----
#define SB_STR 40
#define XWBUF 5120
#define HW_SMEM_FLOATS (4 * XWBUF)           // 81920 B

// ---- agg (fp16) params ----
#define KC 64
#define LSTR 80                              // halfs/row: 64 data + 16 pad (conflict-free LDS.64)
#define AGBUF (128 * LSTR)                   // halfs per buffer
#define AG_SMEM_BYTES (4 * AGBUF * 2)        // 81920 B

#define PSTR (Bx * Nn * OUTd)                // 2,097,152

__device__ __half g_Hth[4 * PSTR];           // relations 0,1,3,4 as [o][m'] fp16 (p16 perm)
__device__ float  g_H3[3 * PSTR];            // identities 2,5,6 as [n][o] fp32
__device__ float  g_P[4 * PSTR];             // partials [n][o]
__device__ float  g_Xr[Bx * Nn * Fdim];      // X rna-rounded, operm (hw)
__device__ float  g_Wt[Rr * OUTd * Fdim];    // W transposed, rna, operm (hw)
__device__ __half g_A1h[Bx * Nn * Nn];       // A1 fp16 [n][m'] (p16)
__device__ __half g_A2h[Bx * Nn * Nn];
__device__ __half g_A1t[Bx * Nn * Nn];       // A1^T fp16 [n][m'] (p16)
__device__ __half g_A2t[Bx * Nn * Nn];

__device__ __forceinline__ float to_tf32(float x) {
    float y; asm("cvt.rna.tf32.f32 %0, %1;" : "=f"(y) : "f"(x)); return y;
}
__device__ __forceinline__ float4 round4(float4 v) {
    v.x = to_tf32(v.x); v.y = to_tf32(v.y); v.z = to_tf32(v.z); v.w = to_tf32(v.w);
    return v;
}
__device__ __forceinline__ void mma8(float* c, const uint32_t* a, uint32_t b0, uint32_t b1) {
    asm volatile(
        "mma.sync.aligned.m16n8k8.row.col.f32.tf32.tf32.f32 "
        "{%0,%1,%2,%3}, {%4,%5,%6,%7}, {%8,%9}, {%0,%1,%2,%3};"
        : "+f"(c[0]), "+f"(c[1]), "+f"(c[2]), "+f"(c[3])
        : "r"(a[0]), "r"(a[1]), "r"(a[2]), "r"(a[3]), "r"(b0), "r"(b1));
}
__device__ __forceinline__ void mma16(float* c, uint32_t a0, uint32_t a1, uint32_t a2,
                                      uint32_t a3, uint32_t b0, uint32_t b1) {
    asm volatile(
        "mma.sync.aligned.m16n8k16.row.col.f32.f16.f16.f32 "
        "{%0,%1,%2,%3}, {%4,%5,%6,%7}, {%8,%9}, {%0,%1,%2,%3};"
        : "+f"(c[0]), "+f"(c[1]), "+f"(c[2]), "+f"(c[3])
        : "r"(a0), "r"(a1), "r"(a2), "r"(a3), "r"(b0), "r"(b1));
}
__device__ __forceinline__ uint32_t fbits(const float* p) { return *(const uint32_t*)p; }
__device__ __forceinline__ uint32_t smem_u32(const void* p) {
    uint32_t a;
    asm("{ .reg .u64 t; cvta.to.shared.u64 t, %1; cvt.u32.u64 %0, t; }" : "=r"(a) : "l"(p));
    return a;
}
// hw's 8-block perm (pairs k,k+4 adjacent)
__device__ __forceinline__ int operm(int n) {
    return (n & ~7) | (((n & 3) << 1) | ((n >> 2) & 1));
}
// fp16 16-block perm: positions 4t+2hi+lo for k=2t+8hi+lo -> {a0,a2}/{b0,b1} are one LDS.64
__device__ __forceinline__ int p16(int k) {
    int k4 = k & 15;
    return (k & ~15) | (((k4 & 7) >> 1) << 2) | (((k4 >> 3) & 1) << 1) | (k4 & 1);
}
#define CPA16(dst, src) \
    asm volatile("cp.async.cg.shared.global [%0], [%1], 16;" :: "r"(dst), "l"(src))
#define CPA_COMMIT() asm volatile("cp.async.commit_group;" ::: "memory")
#define CPA_WAIT0()  asm volatile("cp.async.wait_group 0;" ::: "memory")

// ---------------------------------------------------------------------------
// Prep: g_Xr[m][k'] = rna(X[m][k]), operm
__global__ void xp_kernel(const float* __restrict__ X) {
    int f = blockIdx.x * 256 + threadIdx.x;
    int m = f >> 6, k4 = (f & 63) << 2;
    float4 v = round4(*(const float4*)(X + (size_t)m * Fdim + k4));
    float* dst = g_Xr + (size_t)m * Fdim;
    dst[operm(k4 + 0)] = v.x; dst[operm(k4 + 1)] = v.y;
    dst[operm(k4 + 2)] = v.z; dst[operm(k4 + 3)] = v.w;
}

// Prep: g_Wt[r][o][k'] = rna(W[r][k][o]), operm
__global__ void wt_prep(const float* __restrict__ W) {
    int f = blockIdx.x * 256 + threadIdx.x;
    int r = f >> 14, u = f & 16383, k4 = (u >> 8) << 2, o = u & 255;
    float* dst = g_Wt + ((size_t)r * OUTd + o) * Fdim;
#pragma unroll
    for (int j = 0; j < 4; j++) {
        float v = to_tf32(W[((size_t)r * (Fdim + RELd) + k4 + j) * OUTd + o]);
        dst[operm(k4 + j)] = v;
    }
}

// Prep: A1,A2 -> fp16 in direct [n][m'] and transposed [n][m'] layouts (p16 perm on m).
// 64x64 tiles via smem.
__global__ __launch_bounds__(256) void ah_kernel(const float* __restrict__ A1,
                                                 const float* __restrict__ A2) {
    __shared__ float S[64][65];
    const int tz = blockIdx.z;               // (mat<<3)|b
    const int mat = tz >> 3, b = tz & 7;
    const float* A = (mat ? A2 : A1) + (size_t)b * Nn * Nn;
    __half* Dn = (mat ? g_A2h : g_A1h) + (size_t)b * Nn * Nn;
    __half* Dt = (mat ? g_A2t : g_A1t) + (size_t)b * Nn * Nn;
    const int r0 = blockIdx.y * 64, c0 = blockIdx.x * 64;
    const int tid = threadIdx.x;
    const int rr = tid >> 4, cc = (tid & 15) * 4;

#pragma unroll
    for (int i = 0; i < 4; i++) {
        const int row = rr + i * 16;
        float4 v = *(const float4*)(A + (size_t)(r0 + row) * Nn + c0 + cc);
        S[row][cc] = v.x; S[row][cc + 1] = v.y; S[row][cc + 2] = v.z; S[row][cc + 3] = v.w;
        __half2 h01 = __floats2half2_rn(v.x, v.y);
        __half2 h23 = __floats2half2_rn(v.z, v.w);
        *(__half2*)(Dn + (size_t)(r0 + row) * Nn + c0 + p16(cc))     = h01;
        *(__half2*)(Dn + (size_t)(r0 + row) * Nn + c0 + p16(cc + 2)) = h23;
    }
    __syncthreads();
#pragma unroll
    for (int i = 0; i < 4; i++) {
        const int col = rr + i * 16;
        __half2 h01 = __floats2half2_rn(S[cc][col],     S[cc + 1][col]);
        __half2 h23 = __floats2half2_rn(S[cc + 2][col], S[cc + 3][col]);
        *(__half2*)(Dt + (size_t)(c0 + col) * Nn + r0 + p16(cc))     = h01;
        *(__half2*)(Dt + (size_t)(c0 + col) * Nn + r0 + p16(cc + 2)) = h23;
    }
}

// ---------------------------------------------------------------------------
// HW GEMM (tf32, unchanged mainloop): -> g_Hth fp16 (r=0,1,3,4) or g_H3 fp32 (r=2,5,6)
__global__ __launch_bounds__(256, 2) void hw_mma(const float* __restrict__ W,
                                                 const float* __restrict__ We) {
    extern __shared__ float smf[];
    __shared__ float sCv[128];
    float* sA[2] = { smf, smf + XWBUF };
    float* sB[2] = { smf + 2 * XWBUF, smf + 3 * XWBUF };
    const uint32_t saU[2] = { smem_u32(sA[0]), smem_u32(sA[1]) };
    const uint32_t sbU[2] = { smem_u32(sB[0]), smem_u32(sB[1]) };

    const int tid = threadIdx.x, lane = tid & 31, wid = tid >> 5;
    const int warp_m = (wid & 3) * 32, warp_n = (wid >> 2) * 64;
    const int grp = lane >> 2, tg = lane & 3;

    const int r  = blockIdx.x >> 1;
    const int o0 = (blockIdx.x & 1) * 128;
    const int m0 = blockIdx.y * 128;

    if (tid < 128) {
        float s = 0.f;
#pragma unroll
        for (int d = 0; d < RELd; d++)
            s += We[r * RELd + d] * W[((size_t)r * (Fdim + RELd) + Fdim + d) * OUTd + o0 + tid];
        sCv[tid] = s;
    }

    const float* Xb = g_Xr + (size_t)m0 * Fdim;
    const float* Wt = g_Wt + ((size_t)r * OUTd + o0) * Fdim;

    float acc[2][8][4];
#pragma unroll
    for (int mt = 0; mt < 2; mt++)
#pragma unroll
        for (int nt = 0; nt < 8; nt++)
#pragma unroll
            for (int j = 0; j < 4; j++) acc[mt][nt][j] = 0.f;

    auto loadc = [&](int k0, int s) {
#pragma unroll
        for (int i = 0; i < 4; i++) {
            int f = tid + i * 256, row = f >> 3, s4 = (f & 7) << 2;
            CPA16(saU[s] + (row * SB_STR + s4) * 4, Xb + (size_t)row * Fdim + k0 + s4);
            CPA16(sbU[s] + (row * SB_STR + s4) * 4, Wt + (size_t)row * Fdim + k0 + s4);
        }
    };

    const int NC = Fdim / 32;  // 8
    loadc(0, 0); CPA_COMMIT();

    for (int c = 0; c < NC; c++) {
        const int buf = c & 1;
        CPA_WAIT0();
        __syncthreads();
        if (c + 1 < NC) { loadc((c + 1) * 32, buf ^ 1); CPA_COMMIT(); }

        const float* cA = sA[buf] + 2 * tg;
        const float* cB = sB[buf] + (warp_n + grp) * SB_STR + 2 * tg;
#pragma unroll
        for (int ks = 0; ks < 4; ks++) {
            const int kp = ks * 8;
            float2 va0 = *(const float2*)(cA + (warp_m + grp) * SB_STR + kp);
            float2 vb0 = *(const float2*)(cA + (warp_m + 8 + grp) * SB_STR + kp);
            float2 va1 = *(const float2*)(cA + (warp_m + 16 + grp) * SB_STR + kp);
            float2 vb1 = *(const float2*)(cA + (warp_m + 24 + grp) * SB_STR + kp);
            uint32_t a0[4] = { fbits(&va0.x), fbits(&vb0.x), fbits(&va0.y), fbits(&vb0.y) };
            uint32_t a1[4] = { fbits(&va1.x), fbits(&vb1.x), fbits(&va1.y), fbits(&vb1.y) };
#pragma unroll
            for (int nt = 0; nt < 8; nt++) {
                const float2 bv = *(const float2*)(cB + nt * 8 * SB_STR + kp);
                mma8(acc[0][nt], a0, fbits(&bv.x), fbits(&bv.y));
                mma8(acc[1][nt], a1, fbits(&bv.x), fbits(&bv.y));
            }
        }
    }

    const bool isId = (r == 2 || r == 5 || r == 6);
    if (isId) {
        const int zi = (r == 2) ? 0 : (r == 5) ? 1 : 2;
#pragma unroll
        for (int mt = 0; mt < 2; mt++) {
#pragma unroll
            for (int nt = 0; nt < 8; nt++) {
                const int ol = warp_n + nt * 8 + 2 * tg;
                const float2 cv = *(const float2*)(sCv + ol);
                const int o = o0 + ol;
                int mg = m0 + warp_m + mt * 16 + grp;
                int b = mg >> 10, n = mg & 1023;
                float* dst = g_H3 + (((size_t)(zi * Bx + b) * Nn + n) * OUTd) + o;
                *(float2*)dst = make_float2(to_tf32(acc[mt][nt][0] + cv.x),
                                            to_tf32(acc[mt][nt][1] + cv.y));
                mg += 8; b = mg >> 10; n = mg & 1023;
                dst = g_H3 + (((size_t)(zi * Bx + b) * Nn + n) * OUTd) + o;
                *(float2*)dst = make_float2(to_tf32(acc[mt][nt][2] + cv.x),
                                            to_tf32(acc[mt][nt][3] + cv.y));
            }
        }
    } else {
        const int ti = (r < 2) ? r : r - 1;   // 0,1,3,4 -> 0,1,2,3
#pragma unroll
        for (int mt = 0; mt < 2; mt++) {
#pragma unroll
            for (int nt = 0; nt < 8; nt++) {
                const int ol = warp_n + nt * 8 + 2 * tg;
                const float2 cv = *(const float2*)(sCv + ol);
                const int o = o0 + ol;
                int mg = m0 + warp_m + mt * 16 + grp;
                {
                    int b = mg >> 10, n = mg & 1023, np = p16(n);
                    __half* base = g_Hth + ((size_t)(ti * Bx + b) * OUTd + o) * Nn;
                    base[np]      = __float2half_rn(acc[mt][nt][0] + cv.x);
                    base[Nn + np] = __float2half_rn(acc[mt][nt][1] + cv.y);
                }
                mg += 8;
                {
                    int b = mg >> 10, n = mg & 1023, np = p16(n);
                    __half* base = g_Hth + ((size_t)(ti * Bx + b) * OUTd + o) * Nn;
                    base[np]      = __float2half_rn(acc[mt][nt][2] + cv.x);
                    base[Nn + np] = __float2half_rn(acc[mt][nt][3] + cv.y);
                }
            }
        }
    }
}

// ---------------------------------------------------------------------------
// Aggregation (fp16, unified for all 4 passes): P[p][b][n][o] = L @ R^T
//   p<2:  L = A{1,2}h rows n,  R = Hth[p] rows o
//   p>=2: L = A{1,2}t rows n,  R = Hth[p] rows o
// CTA tile 128x128, KC=64, single-barrier cp.async pipeline, mma.m16n8k16.f16.
__global__ __launch_bounds__(256, 2) void agg_pass(const float* __restrict__ A1,
                                                   const float* __restrict__ A2) {
    extern __shared__ __align__(16) __half smh[];
    __half* sL[2] = { smh, smh + AGBUF };
    __half* sR[2] = { smh + 2 * AGBUF, smh + 3 * AGBUF };
    const uint32_t slU[2] = { smem_u32(sL[0]), smem_u32(sL[1]) };
    const uint32_t srU[2] = { smem_u32(sR[0]), smem_u32(sR[1]) };

    const int tid = threadIdx.x, lane = tid & 31, wid = tid >> 5;
    const int warp_m = (wid & 3) * 32, warp_n = (wid >> 2) * 64;
    const int grp = lane >> 2, tg = lane & 3;

    const int o0 = blockIdx.x * 128;
    const int n0 = blockIdx.y * 128;
    const int z  = blockIdx.z;
    const int b  = z & 7;
    const int p  = z >> 3;
    const int q  = p & 1;

    const __half* Lb = (p < 2 ? (q ? g_A2h : g_A1h) : (q ? g_A2t : g_A1t))
                       + ((size_t)b * Nn + n0) * Nn;
    const __half* Rb = g_Hth + ((size_t)(p * Bx + b) * OUTd + o0) * Nn;
    float* Pout = g_P + (size_t)p * PSTR + (size_t)b * Nn * OUTd;

    float acc[2][8][4];
#pragma unroll
    for (int mt = 0; mt < 2; mt++)
#pragma unroll
        for (int nt = 0; nt < 8; nt++)
#pragma unroll
            for (int j = 0; j < 4; j++) acc[mt][nt][j] = 0.f;

    auto loadc = [&](int k0, int s) {
#pragma unroll
        for (int i = 0; i < 4; i++) {
            int f = tid + i * 256;               // 0..1023
            int row = f >> 3, seg = f & 7;       // 128 rows x 8 segs of 16B
            CPA16(slU[s] + row * (LSTR * 2) + seg * 16, Lb + (size_t)row * Nn + k0 + seg * 8);
            CPA16(srU[s] + row * (LSTR * 2) + seg * 16, Rb + (size_t)row * Nn + k0 + seg * 8);
        }
    };

    const int NC = Nn / KC;  // 16
    loadc(0, 0); CPA_COMMIT();

    for (int c = 0; c < NC; c++) {
        const int buf = c & 1;
        CPA_WAIT0();
        __syncthreads();
        if (c + 1 < NC) { loadc((c + 1) * KC, buf ^ 1); CPA_COMMIT(); }

        const __half* cL = sL[buf];
        const __half* cR = sR[buf];
#pragma unroll
        for (int j16 = 0; j16 < 4; j16++) {
            const int ko = j16 * 16 + 4 * tg;
            uint2 lo0 = *(const uint2*)(cL + (warp_m + grp) * LSTR + ko);
            uint2 hi0 = *(const uint2*)(cL + (warp_m + 8 + grp) * LSTR + ko);
            uint2 lo1 = *(const uint2*)(cL + (warp_m + 16 + grp) * LSTR + ko);
            uint2 hi1 = *(const uint2*)(cL + (warp_m + 24 + grp) * LSTR + ko);
#pragma unroll
            for (int nt = 0; nt < 8; nt++) {
                uint2 bv = *(const uint2*)(cR + (warp_n + nt * 8 + grp) * LSTR + ko);
                mma16(acc[0][nt], lo0.x, hi0.x, lo0.y, hi0.y, bv.x, bv.y);
                mma16(acc[1][nt], lo1.x, hi1.x, lo1.y, hi1.y, bv.x, bv.y);
            }
        }
    }

#pragma unroll
    for (int mt = 0; mt < 2; mt++) {
#pragma unroll
        for (int nt = 0; nt < 8; nt++) {
            const int o = o0 + warp_n + nt * 8 + 2 * tg;
#pragma unroll
            for (int h = 0; h < 2; h++) {
                const int n = n0 + warp_m + mt * 16 + grp + h * 8;
                *(float2*)(Pout + (size_t)n * OUTd + o) =
                    make_float2(acc[mt][nt][2 * h], acc[mt][nt][2 * h + 1]);
            }
        }
    }
}

// ---------------------------------------------------------------------------
__global__ __launch_bounds__(256) void fold_kernel(const float* __restrict__ bias,
                                                   float* __restrict__ out) {
    const int idx = (blockIdx.x * 256 + threadIdx.x) * 4;
    float4 v = *(const float4*)(g_P + idx);
    float4 t;
#pragma unroll
    for (int p = 1; p < 4; p++) {
        t = *(const float4*)(g_P + (size_t)p * PSTR + idx);
        v.x = fmaxf(v.x, t.x); v.y = fmaxf(v.y, t.y);
        v.z = fmaxf(v.z, t.z); v.w = fmaxf(v.w, t.w);
    }
#pragma unroll
    for (int zi = 0; zi < 3; zi++) {
        t = *(const float4*)(g_H3 + (size_t)zi * PSTR + idx);
        v.x = fmaxf(v.x, t.x); v.y = fmaxf(v.y, t.y);
        v.z = fmaxf(v.z, t.z); v.w = fmaxf(v.w, t.w);
    }
    const int bi = idx & (Nn * OUTd - 1);
    t = *(const float4*)(bias + bi);
    v.x += t.x; v.y += t.y; v.z += t.z; v.w += t.w;
    *(float4*)(out + idx) = v;
}

// ---------------------------------------------------------------------------
extern "C" void kernel_launch(void* const* d_in, const int* in_sizes, int n_in,
                              void* d_out, int out_size) {
    const float* X    = (const float*)d_in[0];
    const float* A1   = (const float*)d_in[1];
    const float* A2   = (const float*)d_in[2];
    const float* W    = (const float*)d_in[3];
    const float* We   = (const float*)d_in[4];
    const float* bias = (const float*)d_in[5];
    float* out = (float*)d_out;

    const int hw_smem = HW_SMEM_FLOATS * sizeof(float);
    cudaFuncSetAttribute(hw_mma,   cudaFuncAttributeMaxDynamicSharedMemorySize, hw_smem);
    cudaFuncSetAttribute(agg_pass, cudaFuncAttributeMaxDynamicSharedMemorySize, AG_SMEM_BYTES);

    xp_kernel<<<2048, 256>>>(X);
    wt_prep<<<448, 256>>>(W);
    ah_kernel<<<dim3(16, 16, 16), 256>>>(A1, A2);

    dim3 gHW(14, 64);
    hw_mma<<<gHW, 256, hw_smem>>>(W, We);

    dim3 gAgg(2, 8, 32);
    agg_pass<<<gAgg, 256, AG_SMEM_BYTES>>>(A1, A2);

    fold_kernel<<<(Bx * Nn * OUTd) / 1024, 256>>>(bias, out);
}

// round 12
// speedup vs baseline: 1.5556x; 1.1789x over previous
#include <cuda_runtime.h>
#include <cuda_fp16.h>
#include <cstdint>

#define Bx 8
#define Nn 1024
#define Fdim 256
#define OUTd 256
#define RELd 16
#define Rr 7

// ---- fp16 pipeline params (shared by hw and agg) ----
#define KC 64
#define LSTR 80                              // halfs/row: 64 data + 16 pad (conflict-free LDS.64)
#define AGBUF (128 * LSTR)                   // halfs per buffer
#define AG_SMEM_BYTES (4 * AGBUF * 2)        // 81920 B

#define PSTR (Bx * Nn * OUTd)                // 2,097,152

__device__ __half g_Hth[4 * PSTR];           // relations 0,1,3,4 as [o][m'] fp16 (p16 perm)
__device__ float  g_H3[3 * PSTR];            // identities 2,5,6 as [n][o] fp32
__device__ float  g_P[4 * PSTR];             // partials [n][o]
__device__ __half g_Xh[Bx * Nn * Fdim];      // X fp16 [m][k'] (p16)
__device__ __half g_Wh[Rr * OUTd * Fdim];    // W fp16 transposed [r][o][k'] (p16)
__device__ __half g_A1h[Bx * Nn * Nn];       // A1 fp16 [n][m'] (p16)
__device__ __half g_A2h[Bx * Nn * Nn];
__device__ __half g_A1t[Bx * Nn * Nn];       // A1^T fp16 [n][m'] (p16)
__device__ __half g_A2t[Bx * Nn * Nn];

__device__ __forceinline__ void mma16(float* c, uint32_t a0, uint32_t a1, uint32_t a2,
                                      uint32_t a3, uint32_t b0, uint32_t b1) {
    asm volatile(
        "mma.sync.aligned.m16n8k16.row.col.f32.f16.f16.f32 "
        "{%0,%1,%2,%3}, {%4,%5,%6,%7}, {%8,%9}, {%0,%1,%2,%3};"
        : "+f"(c[0]), "+f"(c[1]), "+f"(c[2]), "+f"(c[3])
        : "r"(a0), "r"(a1), "r"(a2), "r"(a3), "r"(b0), "r"(b1));
}
__device__ __forceinline__ uint32_t smem_u32(const void* p) {
    uint32_t a;
    asm("{ .reg .u64 t; cvta.to.shared.u64 t, %1; cvt.u32.u64 %0, t; }" : "=r"(a) : "l"(p));
    return a;
}
// fp16 16-block perm: pairs (2t,2t+1)->(4t,4t+1), (2t+8,2t+9)->(4t+2,4t+3)
__device__ __forceinline__ int p16(int k) {
    int k4 = k & 15;
    return (k & ~15) | (((k4 & 7) >> 1) << 2) | (((k4 >> 3) & 1) << 1) | (k4 & 1);
}
#define CPA16(dst, src) \
    asm volatile("cp.async.cg.shared.global [%0], [%1], 16;" :: "r"(dst), "l"(src))
#define CPA_COMMIT() asm volatile("cp.async.commit_group;" ::: "memory")
#define CPA_WAIT0()  asm volatile("cp.async.wait_group 0;" ::: "memory")

// ---------------------------------------------------------------------------
// Prep: g_Xh[m][k'] = half(X[m][k]), p16 perm
__global__ void xh_kernel(const float* __restrict__ X) {
    int f = blockIdx.x * 256 + threadIdx.x;       // 524288
    int m = f >> 6, k4 = (f & 63) << 2;
    float4 v = *(const float4*)(X + (size_t)m * Fdim + k4);
    __half* dst = g_Xh + (size_t)m * Fdim;
    *(__half2*)(dst + p16(k4))     = __floats2half2_rn(v.x, v.y);
    *(__half2*)(dst + p16(k4 + 2)) = __floats2half2_rn(v.z, v.w);
}

// Prep: g_Wh[r][o][k'] = half(W[r][k][o]), p16 perm
__global__ void wh_prep(const float* __restrict__ W) {
    int f = blockIdx.x * 256 + threadIdx.x;       // 114688
    int r = f >> 14, u = f & 16383, k4 = (u >> 8) << 2, o = u & 255;
    const float* src = W + ((size_t)r * (Fdim + RELd) + k4) * OUTd + o;
    __half* dst = g_Wh + ((size_t)r * OUTd + o) * Fdim;
    *(__half2*)(dst + p16(k4))     = __floats2half2_rn(src[0], src[OUTd]);
    *(__half2*)(dst + p16(k4 + 2)) = __floats2half2_rn(src[2 * OUTd], src[3 * OUTd]);
}

// Prep: A1,A2 -> fp16 direct [n][m'] and transposed [n][m'] (p16 perm on m)
__global__ __launch_bounds__(256) void ah_kernel(const float* __restrict__ A1,
                                                 const float* __restrict__ A2) {
    __shared__ float S[64][65];
    const int tz = blockIdx.z;               // (mat<<3)|b
    const int mat = tz >> 3, b = tz & 7;
    const float* A = (mat ? A2 : A1) + (size_t)b * Nn * Nn;
    __half* Dn = (mat ? g_A2h : g_A1h) + (size_t)b * Nn * Nn;
    __half* Dt = (mat ? g_A2t : g_A1t) + (size_t)b * Nn * Nn;
    const int r0 = blockIdx.y * 64, c0 = blockIdx.x * 64;
    const int tid = threadIdx.x;
    const int rr = tid >> 4, cc = (tid & 15) * 4;

#pragma unroll
    for (int i = 0; i < 4; i++) {
        const int row = rr + i * 16;
        float4 v = *(const float4*)(A + (size_t)(r0 + row) * Nn + c0 + cc);
        S[row][cc] = v.x; S[row][cc + 1] = v.y; S[row][cc + 2] = v.z; S[row][cc + 3] = v.w;
        *(__half2*)(Dn + (size_t)(r0 + row) * Nn + c0 + p16(cc))     = __floats2half2_rn(v.x, v.y);
        *(__half2*)(Dn + (size_t)(r0 + row) * Nn + c0 + p16(cc + 2)) = __floats2half2_rn(v.z, v.w);
    }
    __syncthreads();
#pragma unroll
    for (int i = 0; i < 4; i++) {
        const int col = rr + i * 16;
        *(__half2*)(Dt + (size_t)(c0 + col) * Nn + r0 + p16(cc)) =
            __floats2half2_rn(S[cc][col], S[cc + 1][col]);
        *(__half2*)(Dt + (size_t)(c0 + col) * Nn + r0 + p16(cc + 2)) =
            __floats2half2_rn(S[cc + 2][col], S[cc + 3][col]);
    }
}

// ---------------------------------------------------------------------------
// HW GEMM (fp16): H[r] = X @ W[r] + c[r]; -> g_Hth fp16 (r=0,1,3,4) / g_H3 fp32 (id)
// CTA tile 128(m) x 128(o), KC=64 (4 chunks), mma.m16n8k16.f16.
__global__ __launch_bounds__(256, 2) void hw_mma(const float* __restrict__ W,
                                                 const float* __restrict__ We) {
    extern __shared__ __align__(16) __half smh[];
    __shared__ float sCv[128];
    __half* sL[2] = { smh, smh + AGBUF };
    __half* sR[2] = { smh + 2 * AGBUF, smh + 3 * AGBUF };
    const uint32_t slU[2] = { smem_u32(sL[0]), smem_u32(sL[1]) };
    const uint32_t srU[2] = { smem_u32(sR[0]), smem_u32(sR[1]) };

    const int tid = threadIdx.x, lane = tid & 31, wid = tid >> 5;
    const int warp_m = (wid & 3) * 32, warp_n = (wid >> 2) * 64;
    const int grp = lane >> 2, tg = lane & 3;

    const int r  = blockIdx.x >> 1;
    const int o0 = (blockIdx.x & 1) * 128;
    const int m0 = blockIdx.y * 128;

    if (tid < 128) {
        float s = 0.f;
#pragma unroll
        for (int d = 0; d < RELd; d++)
            s += We[r * RELd + d] * W[((size_t)r * (Fdim + RELd) + Fdim + d) * OUTd + o0 + tid];
        sCv[tid] = s;
    }

    const __half* Lb = g_Xh + (size_t)m0 * Fdim;
    const __half* Rb = g_Wh + ((size_t)r * OUTd + o0) * Fdim;

    float acc[2][8][4];
#pragma unroll
    for (int mt = 0; mt < 2; mt++)
#pragma unroll
        for (int nt = 0; nt < 8; nt++)
#pragma unroll
            for (int j = 0; j < 4; j++) acc[mt][nt][j] = 0.f;

    auto loadc = [&](int k0, int s) {
#pragma unroll
        for (int i = 0; i < 4; i++) {
            int f = tid + i * 256;
            int row = f >> 3, seg = f & 7;
            CPA16(slU[s] + row * (LSTR * 2) + seg * 16, Lb + (size_t)row * Fdim + k0 + seg * 8);
            CPA16(srU[s] + row * (LSTR * 2) + seg * 16, Rb + (size_t)row * Fdim + k0 + seg * 8);
        }
    };

    const int NC = Fdim / KC;  // 4
    loadc(0, 0); CPA_COMMIT();

    for (int c = 0; c < NC; c++) {
        const int buf = c & 1;
        CPA_WAIT0();
        __syncthreads();
        if (c + 1 < NC) { loadc((c + 1) * KC, buf ^ 1); CPA_COMMIT(); }

        const __half* cL = sL[buf];
        const __half* cR = sR[buf];
#pragma unroll
        for (int j16 = 0; j16 < 4; j16++) {
            const int ko = j16 * 16 + 4 * tg;
            uint2 lo0 = *(const uint2*)(cL + (warp_m + grp) * LSTR + ko);
            uint2 hi0 = *(const uint2*)(cL + (warp_m + 8 + grp) * LSTR + ko);
            uint2 lo1 = *(const uint2*)(cL + (warp_m + 16 + grp) * LSTR + ko);
            uint2 hi1 = *(const uint2*)(cL + (warp_m + 24 + grp) * LSTR + ko);
#pragma unroll
            for (int nt = 0; nt < 8; nt++) {
                uint2 bv = *(const uint2*)(cR + (warp_n + nt * 8 + grp) * LSTR + ko);
                mma16(acc[0][nt], lo0.x, hi0.x, lo0.y, hi0.y, bv.x, bv.y);
                mma16(acc[1][nt], lo1.x, hi1.x, lo1.y, hi1.y, bv.x, bv.y);
            }
        }
    }

    const bool isId = (r == 2 || r == 5 || r == 6);
    if (isId) {
        const int zi = (r == 2) ? 0 : (r == 5) ? 1 : 2;
#pragma unroll
        for (int mt = 0; mt < 2; mt++) {
#pragma unroll
            for (int nt = 0; nt < 8; nt++) {
                const int ol = warp_n + nt * 8 + 2 * tg;
                const float2 cv = *(const float2*)(sCv + ol);
                const int o = o0 + ol;
                int mg = m0 + warp_m + mt * 16 + grp;
                int b = mg >> 10, n = mg & 1023;
                float* dst = g_H3 + (((size_t)(zi * Bx + b) * Nn + n) * OUTd) + o;
                *(float2*)dst = make_float2(acc[mt][nt][0] + cv.x, acc[mt][nt][1] + cv.y);
                mg += 8; b = mg >> 10; n = mg & 1023;
                dst = g_H3 + (((size_t)(zi * Bx + b) * Nn + n) * OUTd) + o;
                *(float2*)dst = make_float2(acc[mt][nt][2] + cv.x, acc[mt][nt][3] + cv.y);
            }
        }
    } else {
        const int ti = (r < 2) ? r : r - 1;   // 0,1,3,4 -> 0,1,2,3
#pragma unroll
        for (int mt = 0; mt < 2; mt++) {
#pragma unroll
            for (int nt = 0; nt < 8; nt++) {
                const int ol = warp_n + nt * 8 + 2 * tg;
                const float2 cv = *(const float2*)(sCv + ol);
                const int o = o0 + ol;
                int mg = m0 + warp_m + mt * 16 + grp;
                {
                    int b = mg >> 10, n = mg & 1023, np = p16(n);
                    __half* base = g_Hth + ((size_t)(ti * Bx + b) * OUTd + o) * Nn;
                    base[np]      = __float2half_rn(acc[mt][nt][0] + cv.x);
                    base[Nn + np] = __float2half_rn(acc[mt][nt][1] + cv.y);
                }
                mg += 8;
                {
                    int b = mg >> 10, n = mg & 1023, np = p16(n);
                    __half* base = g_Hth + ((size_t)(ti * Bx + b) * OUTd + o) * Nn;
                    base[np]      = __float2half_rn(acc[mt][nt][2] + cv.x);
                    base[Nn + np] = __float2half_rn(acc[mt][nt][3] + cv.y);
                }
            }
        }
    }
}

// ---------------------------------------------------------------------------
// Aggregation (fp16, unified): P[p][b][n][o] = L @ R^T  (unchanged from R11)
__global__ __launch_bounds__(256, 2) void agg_pass(const float* __restrict__ A1,
                                                   const float* __restrict__ A2) {
    extern __shared__ __align__(16) __half smh[];
    __half* sL[2] = { smh, smh + AGBUF };
    __half* sR[2] = { smh + 2 * AGBUF, smh + 3 * AGBUF };
    const uint32_t slU[2] = { smem_u32(sL[0]), smem_u32(sL[1]) };
    const uint32_t srU[2] = { smem_u32(sR[0]), smem_u32(sR[1]) };

    const int tid = threadIdx.x, lane = tid & 31, wid = tid >> 5;
    const int warp_m = (wid & 3) * 32, warp_n = (wid >> 2) * 64;
    const int grp = lane >> 2, tg = lane & 3;

    const int o0 = blockIdx.x * 128;
    const int n0 = blockIdx.y * 128;
    const int z  = blockIdx.z;
    const int b  = z & 7;
    const int p  = z >> 3;
    const int q  = p & 1;

    const __half* Lb = (p < 2 ? (q ? g_A2h : g_A1h) : (q ? g_A2t : g_A1t))
                       + ((size_t)b * Nn + n0) * Nn;
    const __half* Rb = g_Hth + ((size_t)(p * Bx + b) * OUTd + o0) * Nn;
    float* Pout = g_P + (size_t)p * PSTR + (size_t)b * Nn * OUTd;

    float acc[2][8][4];
#pragma unroll
    for (int mt = 0; mt < 2; mt++)
#pragma unroll
        for (int nt = 0; nt < 8; nt++)
#pragma unroll
            for (int j = 0; j < 4; j++) acc[mt][nt][j] = 0.f;

    auto loadc = [&](int k0, int s) {
#pragma unroll
        for (int i = 0; i < 4; i++) {
            int f = tid + i * 256;
            int row = f >> 3, seg = f & 7;
            CPA16(slU[s] + row * (LSTR * 2) + seg * 16, Lb + (size_t)row * Nn + k0 + seg * 8);
            CPA16(srU[s] + row * (LSTR * 2) + seg * 16, Rb + (size_t)row * Nn + k0 + seg * 8);
        }
    };

    const int NC = Nn / KC;  // 16
    loadc(0, 0); CPA_COMMIT();

    for (int c = 0; c < NC; c++) {
        const int buf = c & 1;
        CPA_WAIT0();
        __syncthreads();
        if (c + 1 < NC) { loadc((c + 1) * KC, buf ^ 1); CPA_COMMIT(); }

        const __half* cL = sL[buf];
        const __half* cR = sR[buf];
#pragma unroll
        for (int j16 = 0; j16 < 4; j16++) {
            const int ko = j16 * 16 + 4 * tg;
            uint2 lo0 = *(const uint2*)(cL + (warp_m + grp) * LSTR + ko);
            uint2 hi0 = *(const uint2*)(cL + (warp_m + 8 + grp) * LSTR + ko);
            uint2 lo1 = *(const uint2*)(cL + (warp_m + 16 + grp) * LSTR + ko);
            uint2 hi1 = *(const uint2*)(cL + (warp_m + 24 + grp) * LSTR + ko);
#pragma unroll
            for (int nt = 0; nt < 8; nt++) {
                uint2 bv = *(const uint2*)(cR + (warp_n + nt * 8 + grp) * LSTR + ko);
                mma16(acc[0][nt], lo0.x, hi0.x, lo0.y, hi0.y, bv.x, bv.y);
                mma16(acc[1][nt], lo1.x, hi1.x, lo1.y, hi1.y, bv.x, bv.y);
            }
        }
    }

#pragma unroll
    for (int mt = 0; mt < 2; mt++) {
#pragma unroll
        for (int nt = 0; nt < 8; nt++) {
            const int o = o0 + warp_n + nt * 8 + 2 * tg;
#pragma unroll
            for (int h = 0; h < 2; h++) {
                const int n = n0 + warp_m + mt * 16 + grp + h * 8;
                *(float2*)(Pout + (size_t)n * OUTd + o) =
                    make_float2(acc[mt][nt][2 * h], acc[mt][nt][2 * h + 1]);
            }
        }
    }
}

// ---------------------------------------------------------------------------
__global__ __launch_bounds__(256) void fold_kernel(const float* __restrict__ bias,
                                                   float* __restrict__ out) {
    const int idx = (blockIdx.x * 256 + threadIdx.x) * 4;
    float4 v = *(const float4*)(g_P + idx);
    float4 t;
#pragma unroll
    for (int p = 1; p < 4; p++) {
        t = *(const float4*)(g_P + (size_t)p * PSTR + idx);
        v.x = fmaxf(v.x, t.x); v.y = fmaxf(v.y, t.y);
        v.z = fmaxf(v.z, t.z); v.w = fmaxf(v.w, t.w);
    }
#pragma unroll
    for (int zi = 0; zi < 3; zi++) {
        t = *(const float4*)(g_H3 + (size_t)zi * PSTR + idx);
        v.x = fmaxf(v.x, t.x); v.y = fmaxf(v.y, t.y);
        v.z = fmaxf(v.z, t.z); v.w = fmaxf(v.w, t.w);
    }
    const int bi = idx & (Nn * OUTd - 1);
    t = *(const float4*)(bias + bi);
    v.x += t.x; v.y += t.y; v.z += t.z; v.w += t.w;
    *(float4*)(out + idx) = v;
}

// ---------------------------------------------------------------------------
extern "C" void kernel_launch(void* const* d_in, const int* in_sizes, int n_in,
                              void* d_out, int out_size) {
    const float* X    = (const float*)d_in[0];
    const float* A1   = (const float*)d_in[1];
    const float* A2   = (const float*)d_in[2];
    const float* W    = (const float*)d_in[3];
    const float* We   = (const float*)d_in[4];
    const float* bias = (const float*)d_in[5];
    float* out = (float*)d_out;

    cudaFuncSetAttribute(hw_mma,   cudaFuncAttributeMaxDynamicSharedMemorySize, AG_SMEM_BYTES);
    cudaFuncSetAttribute(agg_pass, cudaFuncAttributeMaxDynamicSharedMemorySize, AG_SMEM_BYTES);

    xh_kernel<<<2048, 256>>>(X);
    wh_prep<<<448, 256>>>(W);
    ah_kernel<<<dim3(16, 16, 16), 256>>>(A1, A2);

    dim3 gHW(14, 64);
    hw_mma<<<gHW, 256, AG_SMEM_BYTES>>>(W, We);

    dim3 gAgg(2, 8, 32);
    agg_pass<<<gAgg, 256, AG_SMEM_BYTES>>>(A1, A2);

    fold_kernel<<<(Bx * Nn * OUTd) / 1024, 256>>>(bias, out);
}

// round 13
// speedup vs baseline: 1.5781x; 1.0144x over previous
#include <cuda_runtime.h>
#include <cuda_fp16.h>
#include <cstdint>

#define Bx 8
#define Nn 1024
#define Fdim 256
#define OUTd 256
#define RELd 16
#define Rr 7

// ---- fp16 pipeline params (shared by hw and agg) ----
#define KC 64
#define LSTR 80                              // halfs/row: 64 data + 16 pad (conflict-free LDS.64)
#define AGBUF (128 * LSTR)                   // halfs per buffer
#define AG_SMEM_BYTES (4 * AGBUF * 2)        // 81920 B
#define OSTR 136                             // epilogue staging row: 128 data + 8 pad halfs

#define PSTR (Bx * Nn * OUTd)                // 2,097,152

__device__ __half g_Hth[4 * PSTR];           // relations 0,1,3,4 as [o][m'] fp16 (p16 perm)
__device__ float  g_H3[3 * PSTR];            // identities 2,5,6 as [n][o] fp32
__device__ float  g_P[4 * PSTR];             // partials [n][o]
__device__ __half g_Xh[Bx * Nn * Fdim];      // X fp16 [m][k'] (p16)
__device__ __half g_Wh[Rr * OUTd * Fdim];    // W fp16 transposed [r][o][k'] (p16)
__device__ __half g_A1h[Bx * Nn * Nn];       // A1 fp16 [n][m'] (p16)
__device__ __half g_A2h[Bx * Nn * Nn];
__device__ __half g_A1t[Bx * Nn * Nn];       // A1^T fp16 [n][m'] (p16)
__device__ __half g_A2t[Bx * Nn * Nn];

__device__ __forceinline__ void mma16(float* c, uint32_t a0, uint32_t a1, uint32_t a2,
                                      uint32_t a3, uint32_t b0, uint32_t b1) {
    asm volatile(
        "mma.sync.aligned.m16n8k16.row.col.f32.f16.f16.f32 "
        "{%0,%1,%2,%3}, {%4,%5,%6,%7}, {%8,%9}, {%0,%1,%2,%3};"
        : "+f"(c[0]), "+f"(c[1]), "+f"(c[2]), "+f"(c[3])
        : "r"(a0), "r"(a1), "r"(a2), "r"(a3), "r"(b0), "r"(b1));
}
__device__ __forceinline__ uint32_t smem_u32(const void* p) {
    uint32_t a;
    asm("{ .reg .u64 t; cvta.to.shared.u64 t, %1; cvt.u32.u64 %0, t; }" : "=r"(a) : "l"(p));
    return a;
}
// fp16 16-block perm: pairs (2t,2t+1)->(4t,4t+1), (2t+8,2t+9)->(4t+2,4t+3)
__device__ __forceinline__ int p16(int k) {
    int k4 = k & 15;
    return (k & ~15) | (((k4 & 7) >> 1) << 2) | (((k4 >> 3) & 1) << 1) | (k4 & 1);
}
#define CPA16(dst, src) \
    asm volatile("cp.async.cg.shared.global [%0], [%1], 16;" :: "r"(dst), "l"(src))
#define CPA_COMMIT() asm volatile("cp.async.commit_group;" ::: "memory")
#define CPA_WAIT0()  asm volatile("cp.async.wait_group 0;" ::: "memory")

// ---------------------------------------------------------------------------
// Prep: g_Xh[m][k'] = half(X[m][k]), p16 perm
__global__ void xh_kernel(const float* __restrict__ X) {
    int f = blockIdx.x * 256 + threadIdx.x;       // 524288
    int m = f >> 6, k4 = (f & 63) << 2;
    float4 v = *(const float4*)(X + (size_t)m * Fdim + k4);
    __half* dst = g_Xh + (size_t)m * Fdim;
    *(__half2*)(dst + p16(k4))     = __floats2half2_rn(v.x, v.y);
    *(__half2*)(dst + p16(k4 + 2)) = __floats2half2_rn(v.z, v.w);
}

// Prep: g_Wh[r][o][k'] = half(W[r][k][o]), p16 perm
__global__ void wh_prep(const float* __restrict__ W) {
    int f = blockIdx.x * 256 + threadIdx.x;       // 114688
    int r = f >> 14, u = f & 16383, k4 = (u >> 8) << 2, o = u & 255;
    const float* src = W + ((size_t)r * (Fdim + RELd) + k4) * OUTd + o;
    __half* dst = g_Wh + ((size_t)r * OUTd + o) * Fdim;
    *(__half2*)(dst + p16(k4))     = __floats2half2_rn(src[0], src[OUTd]);
    *(__half2*)(dst + p16(k4 + 2)) = __floats2half2_rn(src[2 * OUTd], src[3 * OUTd]);
}

// Prep: A1,A2 -> fp16 direct [n][m'] and transposed [n][m'] (p16 perm on m)
__global__ __launch_bounds__(256) void ah_kernel(const float* __restrict__ A1,
                                                 const float* __restrict__ A2) {
    __shared__ float S[64][65];
    const int tz = blockIdx.z;               // (mat<<3)|b
    const int mat = tz >> 3, b = tz & 7;
    const float* A = (mat ? A2 : A1) + (size_t)b * Nn * Nn;
    __half* Dn = (mat ? g_A2h : g_A1h) + (size_t)b * Nn * Nn;
    __half* Dt = (mat ? g_A2t : g_A1t) + (size_t)b * Nn * Nn;
    const int r0 = blockIdx.y * 64, c0 = blockIdx.x * 64;
    const int tid = threadIdx.x;
    const int rr = tid >> 4, cc = (tid & 15) * 4;

#pragma unroll
    for (int i = 0; i < 4; i++) {
        const int row = rr + i * 16;
        float4 v = *(const float4*)(A + (size_t)(r0 + row) * Nn + c0 + cc);
        S[row][cc] = v.x; S[row][cc + 1] = v.y; S[row][cc + 2] = v.z; S[row][cc + 3] = v.w;
        *(__half2*)(Dn + (size_t)(r0 + row) * Nn + c0 + p16(cc))     = __floats2half2_rn(v.x, v.y);
        *(__half2*)(Dn + (size_t)(r0 + row) * Nn + c0 + p16(cc + 2)) = __floats2half2_rn(v.z, v.w);
    }
    __syncthreads();
#pragma unroll
    for (int i = 0; i < 4; i++) {
        const int col = rr + i * 16;
        *(__half2*)(Dt + (size_t)(c0 + col) * Nn + r0 + p16(cc)) =
            __floats2half2_rn(S[cc][col], S[cc + 1][col]);
        *(__half2*)(Dt + (size_t)(c0 + col) * Nn + r0 + p16(cc + 2)) =
            __floats2half2_rn(S[cc + 2][col], S[cc + 3][col]);
    }
}

// ---------------------------------------------------------------------------
// HW GEMM (fp16): H[r] = X @ W[r] + c[r]; -> g_Hth fp16 (r=0,1,3,4) / g_H3 fp32 (id)
// CTA tile 128(m) x 128(o), KC=64, mma.m16n8k16.f16. SMEM-staged coalesced epilogue.
__global__ __launch_bounds__(256, 2) void hw_mma(const float* __restrict__ W,
                                                 const float* __restrict__ We) {
    extern __shared__ __align__(16) __half smh[];
    __shared__ float sCv[128];
    __half* sL[2] = { smh, smh + AGBUF };
    __half* sR[2] = { smh + 2 * AGBUF, smh + 3 * AGBUF };
    const uint32_t slU[2] = { smem_u32(sL[0]), smem_u32(sL[1]) };
    const uint32_t srU[2] = { smem_u32(sR[0]), smem_u32(sR[1]) };

    const int tid = threadIdx.x, lane = tid & 31, wid = tid >> 5;
    const int warp_m = (wid & 3) * 32, warp_n = (wid >> 2) * 64;
    const int grp = lane >> 2, tg = lane & 3;

    const int r  = blockIdx.x >> 1;
    const int o0 = (blockIdx.x & 1) * 128;
    const int m0 = blockIdx.y * 128;

    if (tid < 128) {
        float s = 0.f;
#pragma unroll
        for (int d = 0; d < RELd; d++)
            s += We[r * RELd + d] * W[((size_t)r * (Fdim + RELd) + Fdim + d) * OUTd + o0 + tid];
        sCv[tid] = s;
    }

    const __half* Lb = g_Xh + (size_t)m0 * Fdim;
    const __half* Rb = g_Wh + ((size_t)r * OUTd + o0) * Fdim;

    float acc[2][8][4];
#pragma unroll
    for (int mt = 0; mt < 2; mt++)
#pragma unroll
        for (int nt = 0; nt < 8; nt++)
#pragma unroll
            for (int j = 0; j < 4; j++) acc[mt][nt][j] = 0.f;

    auto loadc = [&](int k0, int s) {
#pragma unroll
        for (int i = 0; i < 4; i++) {
            int f = tid + i * 256;
            int row = f >> 3, seg = f & 7;
            CPA16(slU[s] + row * (LSTR * 2) + seg * 16, Lb + (size_t)row * Fdim + k0 + seg * 8);
            CPA16(srU[s] + row * (LSTR * 2) + seg * 16, Rb + (size_t)row * Fdim + k0 + seg * 8);
        }
    };

    const int NC = Fdim / KC;  // 4
    loadc(0, 0); CPA_COMMIT();

    for (int c = 0; c < NC; c++) {
        const int buf = c & 1;
        CPA_WAIT0();
        __syncthreads();
        if (c + 1 < NC) { loadc((c + 1) * KC, buf ^ 1); CPA_COMMIT(); }

        const __half* cL = sL[buf];
        const __half* cR = sR[buf];
#pragma unroll
        for (int j16 = 0; j16 < 4; j16++) {
            const int ko = j16 * 16 + 4 * tg;
            uint2 lo0 = *(const uint2*)(cL + (warp_m + grp) * LSTR + ko);
            uint2 hi0 = *(const uint2*)(cL + (warp_m + 8 + grp) * LSTR + ko);
            uint2 lo1 = *(const uint2*)(cL + (warp_m + 16 + grp) * LSTR + ko);
            uint2 hi1 = *(const uint2*)(cL + (warp_m + 24 + grp) * LSTR + ko);
#pragma unroll
            for (int nt = 0; nt < 8; nt++) {
                uint2 bv = *(const uint2*)(cR + (warp_n + nt * 8 + grp) * LSTR + ko);
                mma16(acc[0][nt], lo0.x, hi0.x, lo0.y, hi0.y, bv.x, bv.y);
                mma16(acc[1][nt], lo1.x, hi1.x, lo1.y, hi1.y, bv.x, bv.y);
            }
        }
    }

    const bool isId = (r == 2 || r == 5 || r == 6);
    if (isId) {
        const int zi = (r == 2) ? 0 : (r == 5) ? 1 : 2;
#pragma unroll
        for (int mt = 0; mt < 2; mt++) {
#pragma unroll
            for (int nt = 0; nt < 8; nt++) {
                const int ol = warp_n + nt * 8 + 2 * tg;
                const float2 cv = *(const float2*)(sCv + ol);
                const int o = o0 + ol;
                int mg = m0 + warp_m + mt * 16 + grp;
                int b = mg >> 10, n = mg & 1023;
                float* dst = g_H3 + (((size_t)(zi * Bx + b) * Nn + n) * OUTd) + o;
                *(float2*)dst = make_float2(acc[mt][nt][0] + cv.x, acc[mt][nt][1] + cv.y);
                mg += 8; b = mg >> 10; n = mg & 1023;
                dst = g_H3 + (((size_t)(zi * Bx + b) * Nn + n) * OUTd) + o;
                *(float2*)dst = make_float2(acc[mt][nt][2] + cv.x, acc[mt][nt][3] + cv.y);
            }
        }
    } else {
        const int ti = (r < 2) ? r : r - 1;   // 0,1,3,4 -> 0,1,2,3
        // stage tile in SMEM (pipeline buffers dead), then coalesced copy-out
        __syncthreads();
        __half* sO = smh;                     // 128 rows(o) x OSTR halfs(m')
#pragma unroll
        for (int mt = 0; mt < 2; mt++) {
#pragma unroll
            for (int nt = 0; nt < 8; nt++) {
                const int ol = warp_n + nt * 8 + 2 * tg;
                const float2 cv = *(const float2*)(sCv + ol);
                const int ml = warp_m + mt * 16 + grp;    // local m (tile is m0-aligned)
                const int np0 = p16(ml), np8 = p16(ml + 8);
                sO[ol * OSTR + np0]       = __float2half_rn(acc[mt][nt][0] + cv.x);
                sO[(ol + 1) * OSTR + np0] = __float2half_rn(acc[mt][nt][1] + cv.y);
                sO[ol * OSTR + np8]       = __float2half_rn(acc[mt][nt][2] + cv.x);
                sO[(ol + 1) * OSTR + np8] = __float2half_rn(acc[mt][nt][3] + cv.y);
            }
        }
        __syncthreads();
        const int b = m0 >> 10, n0l = m0 & 1023;
        __half* Hbase = g_Hth + ((size_t)(ti * Bx + b) * OUTd + o0) * Nn + n0l;
#pragma unroll
        for (int i = 0; i < 8; i++) {
            int f = tid + i * 256;            // 2048 segs: 128 rows x 16 segs of 8 halfs
            int row = f >> 4, seg = f & 15;
            uint4 v = *(const uint4*)(sO + row * OSTR + seg * 8);
            *(uint4*)(Hbase + (size_t)row * Nn + seg * 8) = v;
        }
    }
}

// ---------------------------------------------------------------------------
// Aggregation (fp16, unified): P[p][b][n][o] = L @ R^T  (unchanged)
__global__ __launch_bounds__(256, 2) void agg_pass(const float* __restrict__ A1,
                                                   const float* __restrict__ A2) {
    extern __shared__ __align__(16) __half smh[];
    __half* sL[2] = { smh, smh + AGBUF };
    __half* sR[2] = { smh + 2 * AGBUF, smh + 3 * AGBUF };
    const uint32_t slU[2] = { smem_u32(sL[0]), smem_u32(sL[1]) };
    const uint32_t srU[2] = { smem_u32(sR[0]), smem_u32(sR[1]) };

    const int tid = threadIdx.x, lane = tid & 31, wid = tid >> 5;
    const int warp_m = (wid & 3) * 32, warp_n = (wid >> 2) * 64;
    const int grp = lane >> 2, tg = lane & 3;

    const int o0 = blockIdx.x * 128;
    const int n0 = blockIdx.y * 128;
    const int z  = blockIdx.z;
    const int b  = z & 7;
    const int p  = z >> 3;
    const int q  = p & 1;

    const __half* Lb = (p < 2 ? (q ? g_A2h : g_A1h) : (q ? g_A2t : g_A1t))
                       + ((size_t)b * Nn + n0) * Nn;
    const __half* Rb = g_Hth + ((size_t)(p * Bx + b) * OUTd + o0) * Nn;
    float* Pout = g_P + (size_t)p * PSTR + (size_t)b * Nn * OUTd;

    float acc[2][8][4];
#pragma unroll
    for (int mt = 0; mt < 2; mt++)
#pragma unroll
        for (int nt = 0; nt < 8; nt++)
#pragma unroll
            for (int j = 0; j < 4; j++) acc[mt][nt][j] = 0.f;

    auto loadc = [&](int k0, int s) {
#pragma unroll
        for (int i = 0; i < 4; i++) {
            int f = tid + i * 256;
            int row = f >> 3, seg = f & 7;
            CPA16(slU[s] + row * (LSTR * 2) + seg * 16, Lb + (size_t)row * Nn + k0 + seg * 8);
            CPA16(srU[s] + row * (LSTR * 2) + seg * 16, Rb + (size_t)row * Nn + k0 + seg * 8);
        }
    };

    const int NC = Nn / KC;  // 16
    loadc(0, 0); CPA_COMMIT();

    for (int c = 0; c < NC; c++) {
        const int buf = c & 1;
        CPA_WAIT0();
        __syncthreads();
        if (c + 1 < NC) { loadc((c + 1) * KC, buf ^ 1); CPA_COMMIT(); }

        const __half* cL = sL[buf];
        const __half* cR = sR[buf];
#pragma unroll
        for (int j16 = 0; j16 < 4; j16++) {
            const int ko = j16 * 16 + 4 * tg;
            uint2 lo0 = *(const uint2*)(cL + (warp_m + grp) * LSTR + ko);
            uint2 hi0 = *(const uint2*)(cL + (warp_m + 8 + grp) * LSTR + ko);
            uint2 lo1 = *(const uint2*)(cL + (warp_m + 16 + grp) * LSTR + ko);
            uint2 hi1 = *(const uint2*)(cL + (warp_m + 24 + grp) * LSTR + ko);
#pragma unroll
            for (int nt = 0; nt < 8; nt++) {
                uint2 bv = *(const uint2*)(cR + (warp_n + nt * 8 + grp) * LSTR + ko);
                mma16(acc[0][nt], lo0.x, hi0.x, lo0.y, hi0.y, bv.x, bv.y);
                mma16(acc[1][nt], lo1.x, hi1.x, lo1.y, hi1.y, bv.x, bv.y);
            }
        }
    }

#pragma unroll
    for (int mt = 0; mt < 2; mt++) {
#pragma unroll
        for (int nt = 0; nt < 8; nt++) {
            const int o = o0 + warp_n + nt * 8 + 2 * tg;
#pragma unroll
            for (int h = 0; h < 2; h++) {
                const int n = n0 + warp_m + mt * 16 + grp + h * 8;
                *(float2*)(Pout + (size_t)n * OUTd + o) =
                    make_float2(acc[mt][nt][2 * h], acc[mt][nt][2 * h + 1]);
            }
        }
    }
}

// ---------------------------------------------------------------------------
__global__ __launch_bounds__(256) void fold_kernel(const float* __restrict__ bias,
                                                   float* __restrict__ out) {
    const int idx = (blockIdx.x * 256 + threadIdx.x) * 4;
    float4 v = *(const float4*)(g_P + idx);
    float4 t;
#pragma unroll
    for (int p = 1; p < 4; p++) {
        t = *(const float4*)(g_P + (size_t)p * PSTR + idx);
        v.x = fmaxf(v.x, t.x); v.y = fmaxf(v.y, t.y);
        v.z = fmaxf(v.z, t.z); v.w = fmaxf(v.w, t.w);
    }
#pragma unroll
    for (int zi = 0; zi < 3; zi++) {
        t = *(const float4*)(g_H3 + (size_t)zi * PSTR + idx);
        v.x = fmaxf(v.x, t.x); v.y = fmaxf(v.y, t.y);
        v.z = fmaxf(v.z, t.z); v.w = fmaxf(v.w, t.w);
    }
    const int bi = idx & (Nn * OUTd - 1);
    t = *(const float4*)(bias + bi);
    v.x += t.x; v.y += t.y; v.z += t.z; v.w += t.w;
    *(float4*)(out + idx) = v;
}

// ---------------------------------------------------------------------------
extern "C" void kernel_launch(void* const* d_in, const int* in_sizes, int n_in,
                              void* d_out, int out_size) {
    const float* X    = (const float*)d_in[0];
    const float* A1   = (const float*)d_in[1];
    const float* A2   = (const float*)d_in[2];
    const float* W    = (const float*)d_in[3];
    const float* We   = (const float*)d_in[4];
    const float* bias = (const float*)d_in[5];
    float* out = (float*)d_out;

    cudaFuncSetAttribute(hw_mma,   cudaFuncAttributeMaxDynamicSharedMemorySize, AG_SMEM_BYTES);
    cudaFuncSetAttribute(agg_pass, cudaFuncAttributeMaxDynamicSharedMemorySize, AG_SMEM_BYTES);

    xh_kernel<<<2048, 256>>>(X);
    wh_prep<<<448, 256>>>(W);
    ah_kernel<<<dim3(16, 16, 16), 256>>>(A1, A2);

    dim3 gHW(14, 64);
    hw_mma<<<gHW, 256, AG_SMEM_BYTES>>>(W, We);

    dim3 gAgg(2, 8, 32);
    agg_pass<<<gAgg, 256, AG_SMEM_BYTES>>>(A1, A2);

    fold_kernel<<<(Bx * Nn * OUTd) / 1024, 256>>>(bias, out);
}

// round 15
// speedup vs baseline: 1.6070x; 1.0183x over previous
#include <cuda_runtime.h>
#include <cuda_fp16.h>
#include <cstdint>

#define Bx 8
#define Nn 1024
#define Fdim 256
#define OUTd 256
#define RELd 16
#define Rr 7

// ---- fp16 pipeline params (shared by hw and agg) ----
#define KC 64
#define LSTR 80                              // halfs/row: 64 data + 16 pad (conflict-free LDS.64)
#define AGBUF (128 * LSTR)                   // halfs per buffer
#define AG_SMEM_BYTES (4 * AGBUF * 2)        // 81920 B
#define OSTR 136                             // epilogue staging row: 128 data + 8 pad halfs

#define PSTR (Bx * Nn * OUTd)                // 2,097,152

__device__ __half g_Hth[4 * PSTR];           // relations 0,1,3,4 as [o][m'] fp16 (p16 perm)
__device__ __half g_H3h[3 * PSTR];           // identities 2,5,6 as [n][o] fp16
__device__ __half g_Ph[4 * PSTR];            // partials [n][o] fp16
__device__ __half g_Xh[Bx * Nn * Fdim];      // X fp16 [m][k'] (p16)
__device__ __half g_Wh[Rr * OUTd * Fdim];    // W fp16 transposed [r][o][k'] (p16)
__device__ __half g_A1h[Bx * Nn * Nn];       // A1 fp16 [n][m'] (p16)
__device__ __half g_A2h[Bx * Nn * Nn];
__device__ __half g_A1t[Bx * Nn * Nn];       // A1^T fp16 [n][m'] (p16)
__device__ __half g_A2t[Bx * Nn * Nn];

__device__ __forceinline__ void mma16(float* c, uint32_t a0, uint32_t a1, uint32_t a2,
                                      uint32_t a3, uint32_t b0, uint32_t b1) {
    asm volatile(
        "mma.sync.aligned.m16n8k16.row.col.f32.f16.f16.f32 "
        "{%0,%1,%2,%3}, {%4,%5,%6,%7}, {%8,%9}, {%0,%1,%2,%3};"
        : "+f"(c[0]), "+f"(c[1]), "+f"(c[2]), "+f"(c[3])
        : "r"(a0), "r"(a1), "r"(a2), "r"(a3), "r"(b0), "r"(b1));
}
__device__ __forceinline__ uint32_t smem_u32(const void* p) {
    uint32_t a;
    asm("{ .reg .u64 t; cvta.to.shared.u64 t, %1; cvt.u32.u64 %0, t; }" : "=r"(a) : "l"(p));
    return a;
}
// fp16 16-block perm: pairs (2t,2t+1)->(4t,4t+1), (2t+8,2t+9)->(4t+2,4t+3)
__device__ __forceinline__ int p16(int k) {
    int k4 = k & 15;
    return (k & ~15) | (((k4 & 7) >> 1) << 2) | (((k4 >> 3) & 1) << 1) | (k4 & 1);
}
#define CPA16(dst, src) \
    asm volatile("cp.async.cg.shared.global [%0], [%1], 16;" :: "r"(dst), "l"(src))
#define CPA_COMMIT() asm volatile("cp.async.commit_group;" ::: "memory")
#define CPA_WAIT0()  asm volatile("cp.async.wait_group 0;" ::: "memory")

// ---------------------------------------------------------------------------
// Prep: g_Xh[m][k'] = half(X[m][k]), p16 perm
__global__ void xh_kernel(const float* __restrict__ X) {
    int f = blockIdx.x * 256 + threadIdx.x;       // 524288
    int m = f >> 6, k4 = (f & 63) << 2;
    float4 v = *(const float4*)(X + (size_t)m * Fdim + k4);
    __half* dst = g_Xh + (size_t)m * Fdim;
    *(__half2*)(dst + p16(k4))     = __floats2half2_rn(v.x, v.y);
    *(__half2*)(dst + p16(k4 + 2)) = __floats2half2_rn(v.z, v.w);
}

// Prep: g_Wh[r][o][k'] = half(W[r][k][o]), p16 perm
__global__ void wh_prep(const float* __restrict__ W) {
    int f = blockIdx.x * 256 + threadIdx.x;       // 114688
    int r = f >> 14, u = f & 16383, k4 = (u >> 8) << 2, o = u & 255;
    const float* src = W + ((size_t)r * (Fdim + RELd) + k4) * OUTd + o;
    __half* dst = g_Wh + ((size_t)r * OUTd + o) * Fdim;
    *(__half2*)(dst + p16(k4))     = __floats2half2_rn(src[0], src[OUTd]);
    *(__half2*)(dst + p16(k4 + 2)) = __floats2half2_rn(src[2 * OUTd], src[3 * OUTd]);
}

// Prep: A1,A2 -> fp16 direct [n][m'] and transposed [n][m'] (p16 perm on m)
__global__ __launch_bounds__(256) void ah_kernel(const float* __restrict__ A1,
                                                 const float* __restrict__ A2) {
    __shared__ float S[64][65];
    const int tz = blockIdx.z;               // (mat<<3)|b
    const int mat = tz >> 3, b = tz & 7;
    const float* A = (mat ? A2 : A1) + (size_t)b * Nn * Nn;
    __half* Dn = (mat ? g_A2h : g_A1h) + (size_t)b * Nn * Nn;
    __half* Dt = (mat ? g_A2t : g_A1t) + (size_t)b * Nn * Nn;
    const int r0 = blockIdx.y * 64, c0 = blockIdx.x * 64;
    const int tid = threadIdx.x;
    const int rr = tid >> 4, cc = (tid & 15) * 4;

#pragma unroll
    for (int i = 0; i < 4; i++) {
        const int row = rr + i * 16;
        float4 v = *(const float4*)(A + (size_t)(r0 + row) * Nn + c0 + cc);
        S[row][cc] = v.x; S[row][cc + 1] = v.y; S[row][cc + 2] = v.z; S[row][cc + 3] = v.w;
        *(__half2*)(Dn + (size_t)(r0 + row) * Nn + c0 + p16(cc))     = __floats2half2_rn(v.x, v.y);
        *(__half2*)(Dn + (size_t)(r0 + row) * Nn + c0 + p16(cc + 2)) = __floats2half2_rn(v.z, v.w);
    }
    __syncthreads();
#pragma unroll
    for (int i = 0; i < 4; i++) {
        const int col = rr + i * 16;
        *(__half2*)(Dt + (size_t)(c0 + col) * Nn + r0 + p16(cc)) =
            __floats2half2_rn(S[cc][col], S[cc + 1][col]);
        *(__half2*)(Dt + (size_t)(c0 + col) * Nn + r0 + p16(cc + 2)) =
            __floats2half2_rn(S[cc + 2][col], S[cc + 3][col]);
    }
}

// ---------------------------------------------------------------------------
// HW GEMM (fp16): H[r] = X @ W[r] + c[r]; -> g_Hth fp16 (r=0,1,3,4) / g_H3h fp16 (id)
__global__ __launch_bounds__(256, 2) void hw_mma(const float* __restrict__ W,
                                                 const float* __restrict__ We) {
    extern __shared__ __align__(16) __half smh[];
    __shared__ float sCv[128];
    __half* sL[2] = { smh, smh + AGBUF };
    __half* sR[2] = { smh + 2 * AGBUF, smh + 3 * AGBUF };
    const uint32_t slU[2] = { smem_u32(sL[0]), smem_u32(sL[1]) };
    const uint32_t srU[2] = { smem_u32(sR[0]), smem_u32(sR[1]) };

    const int tid = threadIdx.x, lane = tid & 31, wid = tid >> 5;
    const int warp_m = (wid & 3) * 32, warp_n = (wid >> 2) * 64;
    const int grp = lane >> 2, tg = lane & 3;

    const int r  = blockIdx.x >> 1;
    const int o0 = (blockIdx.x & 1) * 128;
    const int m0 = blockIdx.y * 128;

    if (tid < 128) {
        float s = 0.f;
#pragma unroll
        for (int d = 0; d < RELd; d++)
            s += We[r * RELd + d] * W[((size_t)r * (Fdim + RELd) + Fdim + d) * OUTd + o0 + tid];
        sCv[tid] = s;
    }

    const __half* Lb = g_Xh + (size_t)m0 * Fdim;
    const __half* Rb = g_Wh + ((size_t)r * OUTd + o0) * Fdim;

    float acc[2][8][4];
#pragma unroll
    for (int mt = 0; mt < 2; mt++)
#pragma unroll
        for (int nt = 0; nt < 8; nt++)
#pragma unroll
            for (int j = 0; j < 4; j++) acc[mt][nt][j] = 0.f;

    auto loadc = [&](int k0, int s) {
#pragma unroll
        for (int i = 0; i < 4; i++) {
            int f = tid + i * 256;
            int row = f >> 3, seg = f & 7;
            CPA16(slU[s] + row * (LSTR * 2) + seg * 16, Lb + (size_t)row * Fdim + k0 + seg * 8);
            CPA16(srU[s] + row * (LSTR * 2) + seg * 16, Rb + (size_t)row * Fdim + k0 + seg * 8);
        }
    };

    const int NC = Fdim / KC;  // 4
    loadc(0, 0); CPA_COMMIT();

    for (int c = 0; c < NC; c++) {
        const int buf = c & 1;
        CPA_WAIT0();
        __syncthreads();
        if (c + 1 < NC) { loadc((c + 1) * KC, buf ^ 1); CPA_COMMIT(); }

        const __half* cL = sL[buf];
        const __half* cR = sR[buf];
#pragma unroll
        for (int j16 = 0; j16 < 4; j16++) {
            const int ko = j16 * 16 + 4 * tg;
            uint2 lo0 = *(const uint2*)(cL + (warp_m + grp) * LSTR + ko);
            uint2 hi0 = *(const uint2*)(cL + (warp_m + 8 + grp) * LSTR + ko);
            uint2 lo1 = *(const uint2*)(cL + (warp_m + 16 + grp) * LSTR + ko);
            uint2 hi1 = *(const uint2*)(cL + (warp_m + 24 + grp) * LSTR + ko);
#pragma unroll
            for (int nt = 0; nt < 8; nt++) {
                uint2 bv = *(const uint2*)(cR + (warp_n + nt * 8 + grp) * LSTR + ko);
                mma16(acc[0][nt], lo0.x, hi0.x, lo0.y, hi0.y, bv.x, bv.y);
                mma16(acc[1][nt], lo1.x, hi1.x, lo1.y, hi1.y, bv.x, bv.y);
            }
        }
    }

    const bool isId = (r == 2 || r == 5 || r == 6);
    if (isId) {
        const int zi = (r == 2) ? 0 : (r == 5) ? 1 : 2;
#pragma unroll
        for (int mt = 0; mt < 2; mt++) {
#pragma unroll
            for (int nt = 0; nt < 8; nt++) {
                const int ol = warp_n + nt * 8 + 2 * tg;
                const float2 cv = *(const float2*)(sCv + ol);
                const int o = o0 + ol;
                int mg = m0 + warp_m + mt * 16 + grp;
                int b = mg >> 10, n = mg & 1023;
                __half* dst = g_H3h + (((size_t)(zi * Bx + b) * Nn + n) * OUTd) + o;
                *(__half2*)dst = __floats2half2_rn(acc[mt][nt][0] + cv.x, acc[mt][nt][1] + cv.y);
                mg += 8; b = mg >> 10; n = mg & 1023;
                dst = g_H3h + (((size_t)(zi * Bx + b) * Nn + n) * OUTd) + o;
                *(__half2*)dst = __floats2half2_rn(acc[mt][nt][2] + cv.x, acc[mt][nt][3] + cv.y);
            }
        }
    } else {
        const int ti = (r < 2) ? r : r - 1;   // 0,1,3,4 -> 0,1,2,3
        // stage tile in SMEM (pipeline buffers dead), then coalesced copy-out
        __syncthreads();
        __half* sO = smh;                     // 128 rows(o) x OSTR halfs(m')
#pragma unroll
        for (int mt = 0; mt < 2; mt++) {
#pragma unroll
            for (int nt = 0; nt < 8; nt++) {
                const int ol = warp_n + nt * 8 + 2 * tg;
                const float2 cv = *(const float2*)(sCv + ol);
                const int ml = warp_m + mt * 16 + grp;
                const int np0 = p16(ml), np8 = p16(ml + 8);
                sO[ol * OSTR + np0]       = __float2half_rn(acc[mt][nt][0] + cv.x);
                sO[(ol + 1) * OSTR + np0] = __float2half_rn(acc[mt][nt][1] + cv.y);
                sO[ol * OSTR + np8]       = __float2half_rn(acc[mt][nt][2] + cv.x);
                sO[(ol + 1) * OSTR + np8] = __float2half_rn(acc[mt][nt][3] + cv.y);
            }
        }
        __syncthreads();
        const int b = m0 >> 10, n0l = m0 & 1023;
        __half* Hbase = g_Hth + ((size_t)(ti * Bx + b) * OUTd + o0) * Nn + n0l;
#pragma unroll
        for (int i = 0; i < 8; i++) {
            int f = tid + i * 256;
            int row = f >> 4, seg = f & 15;
            uint4 v = *(const uint4*)(sO + row * OSTR + seg * 8);
            *(uint4*)(Hbase + (size_t)row * Nn + seg * 8) = v;
        }
    }
}

// ---------------------------------------------------------------------------
// Aggregation (fp16, unified): Ph[p][b][n][o] = L @ R^T  (fp16 partial stores)
__global__ __launch_bounds__(256, 2) void agg_pass(const float* __restrict__ A1,
                                                   const float* __restrict__ A2) {
    extern __shared__ __align__(16) __half smh[];
    __half* sL[2] = { smh, smh + AGBUF };
    __half* sR[2] = { smh + 2 * AGBUF, smh + 3 * AGBUF };
    const uint32_t slU[2] = { smem_u32(sL[0]), smem_u32(sL[1]) };
    const uint32_t srU[2] = { smem_u32(sR[0]), smem_u32(sR[1]) };

    const int tid = threadIdx.x, lane = tid & 31, wid = tid >> 5;
    const int warp_m = (wid & 3) * 32, warp_n = (wid >> 2) * 64;
    const int grp = lane >> 2, tg = lane & 3;

    const int o0 = blockIdx.x * 128;
    const int n0 = blockIdx.y * 128;
    const int z  = blockIdx.z;
    const int b  = z & 7;
    const int p  = z >> 3;
    const int q  = p & 1;

    const __half* Lb = (p < 2 ? (q ? g_A2h : g_A1h) : (q ? g_A2t : g_A1t))
                       + ((size_t)b * Nn + n0) * Nn;
    const __half* Rb = g_Hth + ((size_t)(p * Bx + b) * OUTd + o0) * Nn;
    __half* Pout = g_Ph + (size_t)p * PSTR + (size_t)b * Nn * OUTd;

    float acc[2][8][4];
#pragma unroll
    for (int mt = 0; mt < 2; mt++)
#pragma unroll
        for (int nt = 0; nt < 8; nt++)
#pragma unroll
            for (int j = 0; j < 4; j++) acc[mt][nt][j] = 0.f;

    auto loadc = [&](int k0, int s) {
#pragma unroll
        for (int i = 0; i < 4; i++) {
            int f = tid + i * 256;
            int row = f >> 3, seg = f & 7;
            CPA16(slU[s] + row * (LSTR * 2) + seg * 16, Lb + (size_t)row * Nn + k0 + seg * 8);
            CPA16(srU[s] + row * (LSTR * 2) + seg * 16, Rb + (size_t)row * Nn + k0 + seg * 8);
        }
    };

    const int NC = Nn / KC;  // 16
    loadc(0, 0); CPA_COMMIT();

    for (int c = 0; c < NC; c++) {
        const int buf = c & 1;
        CPA_WAIT0();
        __syncthreads();
        if (c + 1 < NC) { loadc((c + 1) * KC, buf ^ 1); CPA_COMMIT(); }

        const __half* cL = sL[buf];
        const __half* cR = sR[buf];
#pragma unroll
        for (int j16 = 0; j16 < 4; j16++) {
            const int ko = j16 * 16 + 4 * tg;
            uint2 lo0 = *(const uint2*)(cL + (warp_m + grp) * LSTR + ko);
            uint2 hi0 = *(const uint2*)(cL + (warp_m + 8 + grp) * LSTR + ko);
            uint2 lo1 = *(const uint2*)(cL + (warp_m + 16 + grp) * LSTR + ko);
            uint2 hi1 = *(const uint2*)(cL + (warp_m + 24 + grp) * LSTR + ko);
#pragma unroll
            for (int nt = 0; nt < 8; nt++) {
                uint2 bv = *(const uint2*)(cR + (warp_n + nt * 8 + grp) * LSTR + ko);
                mma16(acc[0][nt], lo0.x, hi0.x, lo0.y, hi0.y, bv.x, bv.y);
                mma16(acc[1][nt], lo1.x, hi1.x, lo1.y, hi1.y, bv.x, bv.y);
            }
        }
    }

#pragma unroll
    for (int mt = 0; mt < 2; mt++) {
#pragma unroll
        for (int nt = 0; nt < 8; nt++) {
            const int o = o0 + warp_n + nt * 8 + 2 * tg;
#pragma unroll
            for (int h = 0; h < 2; h++) {
                const int n = n0 + warp_m + mt * 16 + grp + h * 8;
                *(__half2*)(Pout + (size_t)n * OUTd + o) =
                    __floats2half2_rn(acc[mt][nt][2 * h], acc[mt][nt][2 * h + 1]);
            }
        }
    }
}

// ---------------------------------------------------------------------------
// out = float( max(Ph0..3, H3h0..2) ) + bias
__global__ __launch_bounds__(256) void fold_kernel(const float* __restrict__ bias,
                                                   float* __restrict__ out) {
    const int idx = (blockIdx.x * 256 + threadIdx.x) * 8;
    uint4 u = *(const uint4*)(g_Ph + idx);
    __half2* hv = (__half2*)&u;
#pragma unroll
    for (int p = 1; p < 4; p++) {
        uint4 t = *(const uint4*)(g_Ph + (size_t)p * PSTR + idx);
        __half2* ht = (__half2*)&t;
#pragma unroll
        for (int j = 0; j < 4; j++) hv[j] = __hmax2(hv[j], ht[j]);
    }
#pragma unroll
    for (int zi = 0; zi < 3; zi++) {
        uint4 t = *(const uint4*)(g_H3h + (size_t)zi * PSTR + idx);
        __half2* ht = (__half2*)&t;
#pragma unroll
        for (int j = 0; j < 4; j++) hv[j] = __hmax2(hv[j], ht[j]);
    }
    const int bi = idx & (Nn * OUTd - 1);
    float4 b0 = *(const float4*)(bias + bi);
    float4 b1 = *(const float4*)(bias + bi + 4);
    float2 f0 = __half22float2(hv[0]), f1 = __half22float2(hv[1]);
    float2 f2 = __half22float2(hv[2]), f3 = __half22float2(hv[3]);
    float4 o0 = make_float4(f0.x + b0.x, f0.y + b0.y, f1.x + b0.z, f1.y + b0.w);
    float4 o1 = make_float4(f2.x + b1.x, f2.y + b1.y, f3.x + b1.z, f3.y + b1.w);
    *(float4*)(out + idx)     = o0;
    *(float4*)(out + idx + 4) = o1;
}

// ---------------------------------------------------------------------------
extern "C" void kernel_launch(void* const* d_in, const int* in_sizes, int n_in,
                              void* d_out, int out_size) {
    const float* X    = (const float*)d_in[0];
    const float* A1   = (const float*)d_in[1];
    const float* A2   = (const float*)d_in[2];
    const float* W    = (const float*)d_in[3];
    const float* We   = (const float*)d_in[4];
    const float* bias = (const float*)d_in[5];
    float* out = (float*)d_out;

    cudaFuncSetAttribute(hw_mma,   cudaFuncAttributeMaxDynamicSharedMemorySize, AG_SMEM_BYTES);
    cudaFuncSetAttribute(agg_pass, cudaFuncAttributeMaxDynamicSharedMemorySize, AG_SMEM_BYTES);

    xh_kernel<<<2048, 256>>>(X);
    wh_prep<<<448, 256>>>(W);
    ah_kernel<<<dim3(16, 16, 16), 256>>>(A1, A2);

    dim3 gHW(14, 64);
    hw_mma<<<gHW, 256, AG_SMEM_BYTES>>>(W, We);

    dim3 gAgg(2, 8, 32);
    agg_pass<<<gAgg, 256, AG_SMEM_BYTES>>>(A1, A2);

    fold_kernel<<<(Bx * Nn * OUTd) / 2048, 256>>>(bias, out);
}

// round 16
// speedup vs baseline: 1.6187x; 1.0073x over previous
#include <cuda_runtime.h>
#include <cuda_fp16.h>
#include <cstdint>

#define Bx 8
#define Nn 1024
#define Fdim 256
#define OUTd 256
#define RELd 16
#define Rr 7

// ---- fp16 pipeline params (shared by hw and agg) ----
#define KC 64
#define LSTR 80                              // halfs/row: 64 data + 16 pad (conflict-free LDS.64)
#define AGBUF (128 * LSTR)                   // halfs per buffer
#define AG_SMEM_BYTES (4 * AGBUF * 2)        // 81920 B
#define OSTR 136                             // epilogue staging row: 128 data + 8 pad halfs

#define PSTR (Bx * Nn * OUTd)                // 2,097,152

__device__ __half g_Hth[4 * PSTR];           // relations 0,1,3,4 as [o][m'] fp16 (p16 perm)
__device__ __half g_H3h[3 * PSTR];           // identities 2,5,6 as [n][o] fp16
__device__ __half g_Ph[4 * PSTR];            // partials [n][o] fp16
__device__ __half g_Xh[Bx * Nn * Fdim];      // X fp16 [m][k'] (p16)
__device__ __half g_Wh[Rr * OUTd * Fdim];    // W fp16 transposed [r][o][k'] (p16)
__device__ __half g_A1h[Bx * Nn * Nn];       // A1 fp16 [n][m'] (p16)
__device__ __half g_A2h[Bx * Nn * Nn];
__device__ __half g_A1t[Bx * Nn * Nn];       // A1^T fp16 [n][m'] (p16)
__device__ __half g_A2t[Bx * Nn * Nn];

__device__ __forceinline__ void mma16(float* c, uint32_t a0, uint32_t a1, uint32_t a2,
                                      uint32_t a3, uint32_t b0, uint32_t b1) {
    asm volatile(
        "mma.sync.aligned.m16n8k16.row.col.f32.f16.f16.f32 "
        "{%0,%1,%2,%3}, {%4,%5,%6,%7}, {%8,%9}, {%0,%1,%2,%3};"
        : "+f"(c[0]), "+f"(c[1]), "+f"(c[2]), "+f"(c[3])
        : "r"(a0), "r"(a1), "r"(a2), "r"(a3), "r"(b0), "r"(b1));
}
__device__ __forceinline__ uint32_t smem_u32(const void* p) {
    uint32_t a;
    asm("{ .reg .u64 t; cvta.to.shared.u64 t, %1; cvt.u32.u64 %0, t; }" : "=r"(a) : "l"(p));
    return a;
}
// fp16 16-block perm: pairs (2t,2t+1)->(4t,4t+1), (2t+8,2t+9)->(4t+2,4t+3)
__device__ __forceinline__ int p16(int k) {
    int k4 = k & 15;
    return (k & ~15) | (((k4 & 7) >> 1) << 2) | (((k4 >> 3) & 1) << 1) | (k4 & 1);
}
#define CPA16(dst, src) \
    asm volatile("cp.async.cg.shared.global [%0], [%1], 16;" :: "r"(dst), "l"(src))
#define CPA_COMMIT() asm volatile("cp.async.commit_group;" ::: "memory")
#define CPA_WAIT0()  asm volatile("cp.async.wait_group 0;" ::: "memory")

// ---------------------------------------------------------------------------
// Prep: g_Xh[m][k'] = half(X[m][k]), p16 perm
__global__ void xh_kernel(const float* __restrict__ X) {
    int f = blockIdx.x * 256 + threadIdx.x;       // 524288
    int m = f >> 6, k4 = (f & 63) << 2;
    float4 v = *(const float4*)(X + (size_t)m * Fdim + k4);
    __half* dst = g_Xh + (size_t)m * Fdim;
    *(__half2*)(dst + p16(k4))     = __floats2half2_rn(v.x, v.y);
    *(__half2*)(dst + p16(k4 + 2)) = __floats2half2_rn(v.z, v.w);
}

// Prep: g_Wh[r][o][k'] = half(W[r][k][o]), p16 perm
__global__ void wh_prep(const float* __restrict__ W) {
    int f = blockIdx.x * 256 + threadIdx.x;       // 114688
    int r = f >> 14, u = f & 16383, k4 = (u >> 8) << 2, o = u & 255;
    const float* src = W + ((size_t)r * (Fdim + RELd) + k4) * OUTd + o;
    __half* dst = g_Wh + ((size_t)r * OUTd + o) * Fdim;
    *(__half2*)(dst + p16(k4))     = __floats2half2_rn(src[0], src[OUTd]);
    *(__half2*)(dst + p16(k4 + 2)) = __floats2half2_rn(src[2 * OUTd], src[3 * OUTd]);
}

// Prep: A1,A2 -> fp16 direct [n][m'] and transposed [n][m'] (p16 perm on m)
__global__ __launch_bounds__(256) void ah_kernel(const float* __restrict__ A1,
                                                 const float* __restrict__ A2) {
    __shared__ float S[64][65];
    const int tz = blockIdx.z;               // (mat<<3)|b
    const int mat = tz >> 3, b = tz & 7;
    const float* A = (mat ? A2 : A1) + (size_t)b * Nn * Nn;
    __half* Dn = (mat ? g_A2h : g_A1h) + (size_t)b * Nn * Nn;
    __half* Dt = (mat ? g_A2t : g_A1t) + (size_t)b * Nn * Nn;
    const int r0 = blockIdx.y * 64, c0 = blockIdx.x * 64;
    const int tid = threadIdx.x;
    const int rr = tid >> 4, cc = (tid & 15) * 4;

#pragma unroll
    for (int i = 0; i < 4; i++) {
        const int row = rr + i * 16;
        float4 v = *(const float4*)(A + (size_t)(r0 + row) * Nn + c0 + cc);
        S[row][cc] = v.x; S[row][cc + 1] = v.y; S[row][cc + 2] = v.z; S[row][cc + 3] = v.w;
        *(__half2*)(Dn + (size_t)(r0 + row) * Nn + c0 + p16(cc))     = __floats2half2_rn(v.x, v.y);
        *(__half2*)(Dn + (size_t)(r0 + row) * Nn + c0 + p16(cc + 2)) = __floats2half2_rn(v.z, v.w);
    }
    __syncthreads();
#pragma unroll
    for (int i = 0; i < 4; i++) {
        const int col = rr + i * 16;
        *(__half2*)(Dt + (size_t)(c0 + col) * Nn + r0 + p16(cc)) =
            __floats2half2_rn(S[cc][col], S[cc + 1][col]);
        *(__half2*)(Dt + (size_t)(c0 + col) * Nn + r0 + p16(cc + 2)) =
            __floats2half2_rn(S[cc + 2][col], S[cc + 3][col]);
    }
}

// ---------------------------------------------------------------------------
// HW GEMM (fp16): H[r] = X @ W[r] + c[r]; -> g_Hth fp16 (r=0,1,3,4) / g_H3h fp16 (id)
__global__ __launch_bounds__(256, 2) void hw_mma(const float* __restrict__ W,
                                                 const float* __restrict__ We) {
    extern __shared__ __align__(16) __half smh[];
    __shared__ float sCv[128];
    __half* sL[2] = { smh, smh + AGBUF };
    __half* sR[2] = { smh + 2 * AGBUF, smh + 3 * AGBUF };
    const uint32_t slU[2] = { smem_u32(sL[0]), smem_u32(sL[1]) };
    const uint32_t srU[2] = { smem_u32(sR[0]), smem_u32(sR[1]) };

    const int tid = threadIdx.x, lane = tid & 31, wid = tid >> 5;
    const int warp_m = (wid & 3) * 32, warp_n = (wid >> 2) * 64;
    const int grp = lane >> 2, tg = lane & 3;

    const int r  = blockIdx.x >> 1;
    const int o0 = (blockIdx.x & 1) * 128;
    const int m0 = blockIdx.y * 128;

    if (tid < 128) {
        float s = 0.f;
#pragma unroll
        for (int d = 0; d < RELd; d++)
            s += We[r * RELd + d] * W[((size_t)r * (Fdim + RELd) + Fdim + d) * OUTd + o0 + tid];
        sCv[tid] = s;
    }

    const __half* Lb = g_Xh + (size_t)m0 * Fdim;
    const __half* Rb = g_Wh + ((size_t)r * OUTd + o0) * Fdim;

    float acc[2][8][4];
#pragma unroll
    for (int mt = 0; mt < 2; mt++)
#pragma unroll
        for (int nt = 0; nt < 8; nt++)
#pragma unroll
            for (int j = 0; j < 4; j++) acc[mt][nt][j] = 0.f;

    auto loadc = [&](int k0, int s) {
#pragma unroll
        for (int i = 0; i < 4; i++) {
            int f = tid + i * 256;
            int row = f >> 3, seg = f & 7;
            CPA16(slU[s] + row * (LSTR * 2) + seg * 16, Lb + (size_t)row * Fdim + k0 + seg * 8);
            CPA16(srU[s] + row * (LSTR * 2) + seg * 16, Rb + (size_t)row * Fdim + k0 + seg * 8);
        }
    };

    const int NC = Fdim / KC;  // 4
    loadc(0, 0); CPA_COMMIT();

    for (int c = 0; c < NC; c++) {
        const int buf = c & 1;
        CPA_WAIT0();
        __syncthreads();
        if (c + 1 < NC) { loadc((c + 1) * KC, buf ^ 1); CPA_COMMIT(); }

        const __half* cL = sL[buf];
        const __half* cR = sR[buf];
#pragma unroll
        for (int j16 = 0; j16 < 4; j16++) {
            const int ko = j16 * 16 + 4 * tg;
            uint2 lo0 = *(const uint2*)(cL + (warp_m + grp) * LSTR + ko);
            uint2 hi0 = *(const uint2*)(cL + (warp_m + 8 + grp) * LSTR + ko);
            uint2 lo1 = *(const uint2*)(cL + (warp_m + 16 + grp) * LSTR + ko);
            uint2 hi1 = *(const uint2*)(cL + (warp_m + 24 + grp) * LSTR + ko);
#pragma unroll
            for (int nt = 0; nt < 8; nt++) {
                uint2 bv = *(const uint2*)(cR + (warp_n + nt * 8 + grp) * LSTR + ko);
                mma16(acc[0][nt], lo0.x, hi0.x, lo0.y, hi0.y, bv.x, bv.y);
                mma16(acc[1][nt], lo1.x, hi1.x, lo1.y, hi1.y, bv.x, bv.y);
            }
        }
    }

    const bool isId = (r == 2 || r == 5 || r == 6);
    if (isId) {
        const int zi = (r == 2) ? 0 : (r == 5) ? 1 : 2;
#pragma unroll
        for (int mt = 0; mt < 2; mt++) {
#pragma unroll
            for (int nt = 0; nt < 8; nt++) {
                const int ol = warp_n + nt * 8 + 2 * tg;
                const float2 cv = *(const float2*)(sCv + ol);
                const int o = o0 + ol;
                int mg = m0 + warp_m + mt * 16 + grp;
                int b = mg >> 10, n = mg & 1023;
                __half* dst = g_H3h + (((size_t)(zi * Bx + b) * Nn + n) * OUTd) + o;
                *(__half2*)dst = __floats2half2_rn(acc[mt][nt][0] + cv.x, acc[mt][nt][1] + cv.y);
                mg += 8; b = mg >> 10; n = mg & 1023;
                dst = g_H3h + (((size_t)(zi * Bx + b) * Nn + n) * OUTd) + o;
                *(__half2*)dst = __floats2half2_rn(acc[mt][nt][2] + cv.x, acc[mt][nt][3] + cv.y);
            }
        }
    } else {
        const int ti = (r < 2) ? r : r - 1;   // 0,1,3,4 -> 0,1,2,3
        __syncthreads();
        __half* sO = smh;                     // 128 rows(o) x OSTR halfs(m')
#pragma unroll
        for (int mt = 0; mt < 2; mt++) {
#pragma unroll
            for (int nt = 0; nt < 8; nt++) {
                const int ol = warp_n + nt * 8 + 2 * tg;
                const float2 cv = *(const float2*)(sCv + ol);
                const int ml = warp_m + mt * 16 + grp;
                const int np0 = p16(ml), np8 = p16(ml + 8);
                sO[ol * OSTR + np0]       = __float2half_rn(acc[mt][nt][0] + cv.x);
                sO[(ol + 1) * OSTR + np0] = __float2half_rn(acc[mt][nt][1] + cv.y);
                sO[ol * OSTR + np8]       = __float2half_rn(acc[mt][nt][2] + cv.x);
                sO[(ol + 1) * OSTR + np8] = __float2half_rn(acc[mt][nt][3] + cv.y);
            }
        }
        __syncthreads();
        const int b = m0 >> 10, n0l = m0 & 1023;
        __half* Hbase = g_Hth + ((size_t)(ti * Bx + b) * OUTd + o0) * Nn + n0l;
#pragma unroll
        for (int i = 0; i < 8; i++) {
            int f = tid + i * 256;
            int row = f >> 4, seg = f & 15;
            uint4 v = *(const uint4*)(sO + row * OSTR + seg * 8);
            *(uint4*)(Hbase + (size_t)row * Nn + seg * 8) = v;
        }
    }
}

// ---------------------------------------------------------------------------
// Aggregation (fp16, unified): Ph[p][b][n][o] = L @ R^T  (fp16 partial stores)
__global__ __launch_bounds__(256, 2) void agg_pass(const float* __restrict__ A1,
                                                   const float* __restrict__ A2) {
    extern __shared__ __align__(16) __half smh[];
    __half* sL[2] = { smh, smh + AGBUF };
    __half* sR[2] = { smh + 2 * AGBUF, smh + 3 * AGBUF };
    const uint32_t slU[2] = { smem_u32(sL[0]), smem_u32(sL[1]) };
    const uint32_t srU[2] = { smem_u32(sR[0]), smem_u32(sR[1]) };

    const int tid = threadIdx.x, lane = tid & 31, wid = tid >> 5;
    const int warp_m = (wid & 3) * 32, warp_n = (wid >> 2) * 64;
    const int grp = lane >> 2, tg = lane & 3;

    const int o0 = blockIdx.x * 128;
    const int n0 = blockIdx.y * 128;
    const int z  = blockIdx.z;
    const int b  = z & 7;
    const int p  = z >> 3;
    const int q  = p & 1;

    const __half* Lb = (p < 2 ? (q ? g_A2h : g_A1h) : (q ? g_A2t : g_A1t))
                       + ((size_t)b * Nn + n0) * Nn;
    const __half* Rb = g_Hth + ((size_t)(p * Bx + b) * OUTd + o0) * Nn;
    __half* Pout = g_Ph + (size_t)p * PSTR + (size_t)b * Nn * OUTd;

    float acc[2][8][4];
#pragma unroll
    for (int mt = 0; mt < 2; mt++)
#pragma unroll
        for (int nt = 0; nt < 8; nt++)
#pragma unroll
            for (int j = 0; j < 4; j++) acc[mt][nt][j] = 0.f;

    auto loadc = [&](int k0, int s) {
#pragma unroll
        for (int i = 0; i < 4; i++) {
            int f = tid + i * 256;
            int row = f >> 3, seg = f & 7;
            CPA16(slU[s] + row * (LSTR * 2) + seg * 16, Lb + (size_t)row * Nn + k0 + seg * 8);
            CPA16(srU[s] + row * (LSTR * 2) + seg * 16, Rb + (size_t)row * Nn + k0 + seg * 8);
        }
    };

    const int NC = Nn / KC;  // 16
    loadc(0, 0); CPA_COMMIT();

    for (int c = 0; c < NC; c++) {
        const int buf = c & 1;
        CPA_WAIT0();
        __syncthreads();
        if (c + 1 < NC) { loadc((c + 1) * KC, buf ^ 1); CPA_COMMIT(); }

        const __half* cL = sL[buf];
        const __half* cR = sR[buf];
#pragma unroll
        for (int j16 = 0; j16 < 4; j16++) {
            const int ko = j16 * 16 + 4 * tg;
            uint2 lo0 = *(const uint2*)(cL + (warp_m + grp) * LSTR + ko);
            uint2 hi0 = *(const uint2*)(cL + (warp_m + 8 + grp) * LSTR + ko);
            uint2 lo1 = *(const uint2*)(cL + (warp_m + 16 + grp) * LSTR + ko);
            uint2 hi1 = *(const uint2*)(cL + (warp_m + 24 + grp) * LSTR + ko);
#pragma unroll
            for (int nt = 0; nt < 8; nt++) {
                uint2 bv = *(const uint2*)(cR + (warp_n + nt * 8 + grp) * LSTR + ko);
                mma16(acc[0][nt], lo0.x, hi0.x, lo0.y, hi0.y, bv.x, bv.y);
                mma16(acc[1][nt], lo1.x, hi1.x, lo1.y, hi1.y, bv.x, bv.y);
            }
        }
    }

#pragma unroll
    for (int mt = 0; mt < 2; mt++) {
#pragma unroll
        for (int nt = 0; nt < 8; nt++) {
            const int o = o0 + warp_n + nt * 8 + 2 * tg;
#pragma unroll
            for (int h = 0; h < 2; h++) {
                const int n = n0 + warp_m + mt * 16 + grp + h * 8;
                *(__half2*)(Pout + (size_t)n * OUTd + o) =
                    __floats2half2_rn(acc[mt][nt][2 * h], acc[mt][nt][2 * h + 1]);
            }
        }
    }
}

// ---------------------------------------------------------------------------
// out = float( max(Ph0..3, H3h0..2) ) + bias
__global__ __launch_bounds__(256) void fold_kernel(const float* __restrict__ bias,
                                                   float* __restrict__ out) {
    const int idx = (blockIdx.x * 256 + threadIdx.x) * 8;
    uint4 u = *(const uint4*)(g_Ph + idx);
    __half2* hv = (__half2*)&u;
#pragma unroll
    for (int p = 1; p < 4; p++) {
        uint4 t = *(const uint4*)(g_Ph + (size_t)p * PSTR + idx);
        __half2* ht = (__half2*)&t;
#pragma unroll
        for (int j = 0; j < 4; j++) hv[j] = __hmax2(hv[j], ht[j]);
    }
#pragma unroll
    for (int zi = 0; zi < 3; zi++) {
        uint4 t = *(const uint4*)(g_H3h + (size_t)zi * PSTR + idx);
        __half2* ht = (__half2*)&t;
#pragma unroll
        for (int j = 0; j < 4; j++) hv[j] = __hmax2(hv[j], ht[j]);
    }
    const int bi = idx & (Nn * OUTd - 1);
    float4 b0 = *(const float4*)(bias + bi);
    float4 b1 = *(const float4*)(bias + bi + 4);
    float2 f0 = __half22float2(hv[0]), f1 = __half22float2(hv[1]);
    float2 f2 = __half22float2(hv[2]), f3 = __half22float2(hv[3]);
    float4 o0 = make_float4(f0.x + b0.x, f0.y + b0.y, f1.x + b0.z, f1.y + b0.w);
    float4 o1 = make_float4(f2.x + b1.x, f2.y + b1.y, f3.x + b1.z, f3.y + b1.w);
    *(float4*)(out + idx)     = o0;
    *(float4*)(out + idx + 4) = o1;
}

// ---------------------------------------------------------------------------
extern "C" void kernel_launch(void* const* d_in, const int* in_sizes, int n_in,
                              void* d_out, int out_size) {
    const float* X    = (const float*)d_in[0];
    const float* A1   = (const float*)d_in[1];
    const float* A2   = (const float*)d_in[2];
    const float* W    = (const float*)d_in[3];
    const float* We   = (const float*)d_in[4];
    const float* bias = (const float*)d_in[5];
    float* out = (float*)d_out;

    static cudaStream_t s2 = nullptr;
    static cudaEvent_t evFork = nullptr, evJoin = nullptr;
    if (s2 == nullptr) {
        cudaStreamCreateWithFlags(&s2, cudaStreamNonBlocking);
        cudaEventCreateWithFlags(&evFork, cudaEventDisableTiming);
        cudaEventCreateWithFlags(&evJoin, cudaEventDisableTiming);
        cudaFuncSetAttribute(hw_mma,   cudaFuncAttributeMaxDynamicSharedMemorySize, AG_SMEM_BYTES);
        cudaFuncSetAttribute(agg_pass, cudaFuncAttributeMaxDynamicSharedMemorySize, AG_SMEM_BYTES);
    }

    // fork: ah_kernel (A -> fp16, both layouts) runs concurrently with X/W prep + hw GEMM
    cudaEventRecord(evFork, 0);
    cudaStreamWaitEvent(s2, evFork, 0);
    ah_kernel<<<dim3(16, 16, 16), 256, 0, s2>>>(A1, A2);
    cudaEventRecord(evJoin, s2);

    xh_kernel<<<2048, 256>>>(X);
    wh_prep<<<448, 256>>>(W);

    dim3 gHW(14, 64);
    hw_mma<<<gHW, 256, AG_SMEM_BYTES>>>(W, We);

    // join: agg needs both ah (A fp16) and hw (Hth)
    cudaStreamWaitEvent(0, evJoin, 0);

    dim3 gAgg(2, 8, 32);
    agg_pass<<<gAgg, 256, AG_SMEM_BYTES>>>(A1, A2);

    fold_kernel<<<(Bx * Nn * OUTd) / 2048, 256>>>(bias, out);
}

// round 17
// speedup vs baseline: 1.9506x; 1.2051x over previous
#include <cuda_runtime.h>
#include <cuda_fp16.h>
#include <cstdint>

#define Bx 8
#define Nn 1024
#define Fdim 256
#define OUTd 256
#define RELd 16
#define Rr 7

// ---- fp16 pipeline params (shared by hw and agg) ----
#define KC 64
#define LSTR 72                              // halfs/row: 64 data + 8 pad (144B = 9*16B, LDSM conflict-free)
#define AGBUF (128 * LSTR)                   // halfs per buffer
#define AG_SMEM_BYTES (4 * AGBUF * 2)        // 73728 B
#define OSTR 136                             // epilogue staging row: 128 data + 8 pad halfs

#define PSTR (Bx * Nn * OUTd)                // 2,097,152

__device__ __half g_Hth[4 * PSTR];           // relations 0,1,3,4 as [o][m] fp16 (plain)
__device__ __half g_H3h[3 * PSTR];           // identities 2,5,6 as [n][o] fp16
__device__ __half g_Ph[4 * PSTR];            // partials [n][o] fp16
__device__ __half g_Xh[Bx * Nn * Fdim];      // X fp16 [m][k] (plain)
__device__ __half g_Wh[Rr * OUTd * Fdim];    // W fp16 transposed [r][o][k] (plain)
__device__ __half g_A1h[Bx * Nn * Nn];       // A1 fp16 [n][m]
__device__ __half g_A2h[Bx * Nn * Nn];
__device__ __half g_A1t[Bx * Nn * Nn];       // A1^T fp16 [n][m]
__device__ __half g_A2t[Bx * Nn * Nn];

__device__ __forceinline__ void mma16(float* c, uint32_t a0, uint32_t a1, uint32_t a2,
                                      uint32_t a3, uint32_t b0, uint32_t b1) {
    asm volatile(
        "mma.sync.aligned.m16n8k16.row.col.f32.f16.f16.f32 "
        "{%0,%1,%2,%3}, {%4,%5,%6,%7}, {%8,%9}, {%0,%1,%2,%3};"
        : "+f"(c[0]), "+f"(c[1]), "+f"(c[2]), "+f"(c[3])
        : "r"(a0), "r"(a1), "r"(a2), "r"(a3), "r"(b0), "r"(b1));
}
__device__ __forceinline__ void ldsm4(uint32_t& r0, uint32_t& r1, uint32_t& r2,
                                      uint32_t& r3, uint32_t a) {
    asm volatile("ldmatrix.sync.aligned.m8n8.x4.shared.b16 {%0,%1,%2,%3}, [%4];"
                 : "=r"(r0), "=r"(r1), "=r"(r2), "=r"(r3) : "r"(a));
}
__device__ __forceinline__ uint32_t smem_u32(const void* p) {
    uint32_t a;
    asm("{ .reg .u64 t; cvta.to.shared.u64 t, %1; cvt.u32.u64 %0, t; }" : "=r"(a) : "l"(p));
    return a;
}
#define CPA16(dst, src) \
    asm volatile("cp.async.cg.shared.global [%0], [%1], 16;" :: "r"(dst), "l"(src))
#define CPA_COMMIT() asm volatile("cp.async.commit_group;" ::: "memory")
#define CPA_WAIT0()  asm volatile("cp.async.wait_group 0;" ::: "memory")

// Per-lane LDSM address offsets (halfs):
//  A-operand x4 (rows m..m+15, k and k+8): row = lane&15, kadd = (lane>>4)*8
//  B-operand x4 (rows n..n+15 pair, k/k+8): row = ((lane>>4)&1)*8 + (lane&7), kadd = ((lane>>3)&1)*8
__device__ __forceinline__ uint32_t laneL_off(int lane) {
    return ((lane & 15) * LSTR + (lane >> 4) * 8) * 2;
}
__device__ __forceinline__ uint32_t laneR_off(int lane) {
    return ((((lane >> 4) & 1) * 8 + (lane & 7)) * LSTR + ((lane >> 3) & 1) * 8) * 2;
}

// ---------------------------------------------------------------------------
// Prep: g_Xh[m][k] = half(X[m][k])
__global__ void xh_kernel(const float* __restrict__ X) {
    int f = blockIdx.x * 256 + threadIdx.x;       // 524288
    int m = f >> 6, k4 = (f & 63) << 2;
    float4 v = *(const float4*)(X + (size_t)m * Fdim + k4);
    __half* dst = g_Xh + (size_t)m * Fdim + k4;
    *(__half2*)(dst)     = __floats2half2_rn(v.x, v.y);
    *(__half2*)(dst + 2) = __floats2half2_rn(v.z, v.w);
}

// Prep: g_Wh[r][o][k] = half(W[r][k][o])
__global__ void wh_prep(const float* __restrict__ W) {
    int f = blockIdx.x * 256 + threadIdx.x;       // 114688
    int r = f >> 14, u = f & 16383, k4 = (u >> 8) << 2, o = u & 255;
    const float* src = W + ((size_t)r * (Fdim + RELd) + k4) * OUTd + o;
    __half* dst = g_Wh + ((size_t)r * OUTd + o) * Fdim + k4;
    *(__half2*)(dst)     = __floats2half2_rn(src[0], src[OUTd]);
    *(__half2*)(dst + 2) = __floats2half2_rn(src[2 * OUTd], src[3 * OUTd]);
}

// Prep: A1,A2 -> fp16 direct [n][m] and transposed [n][m]
__global__ __launch_bounds__(256) void ah_kernel(const float* __restrict__ A1,
                                                 const float* __restrict__ A2) {
    __shared__ float S[64][65];
    const int tz = blockIdx.z;               // (mat<<3)|b
    const int mat = tz >> 3, b = tz & 7;
    const float* A = (mat ? A2 : A1) + (size_t)b * Nn * Nn;
    __half* Dn = (mat ? g_A2h : g_A1h) + (size_t)b * Nn * Nn;
    __half* Dt = (mat ? g_A2t : g_A1t) + (size_t)b * Nn * Nn;
    const int r0 = blockIdx.y * 64, c0 = blockIdx.x * 64;
    const int tid = threadIdx.x;
    const int rr = tid >> 4, cc = (tid & 15) * 4;

#pragma unroll
    for (int i = 0; i < 4; i++) {
        const int row = rr + i * 16;
        float4 v = *(const float4*)(A + (size_t)(r0 + row) * Nn + c0 + cc);
        S[row][cc] = v.x; S[row][cc + 1] = v.y; S[row][cc + 2] = v.z; S[row][cc + 3] = v.w;
        __half* d = Dn + (size_t)(r0 + row) * Nn + c0 + cc;
        *(__half2*)(d)     = __floats2half2_rn(v.x, v.y);
        *(__half2*)(d + 2) = __floats2half2_rn(v.z, v.w);
    }
    __syncthreads();
#pragma unroll
    for (int i = 0; i < 4; i++) {
        const int col = rr + i * 16;
        __half* d = Dt + (size_t)(c0 + col) * Nn + r0 + cc;
        *(__half2*)(d)     = __floats2half2_rn(S[cc][col],     S[cc + 1][col]);
        *(__half2*)(d + 2) = __floats2half2_rn(S[cc + 2][col], S[cc + 3][col]);
    }
}

// ---------------------------------------------------------------------------
// HW GEMM (fp16, LDSM): H[r] = X @ W[r] + c[r]; -> g_Hth (r=0,1,3,4) / g_H3h (id)
__global__ __launch_bounds__(256, 2) void hw_mma(const float* __restrict__ W,
                                                 const float* __restrict__ We) {
    extern __shared__ __align__(16) __half smh[];
    __shared__ float sCv[128];
    const uint32_t smU = smem_u32(smh);
    const uint32_t slU[2] = { smU, smU + AGBUF * 2 };
    const uint32_t srU[2] = { smU + 2 * AGBUF * 2, smU + 3 * AGBUF * 2 };

    const int tid = threadIdx.x, lane = tid & 31, wid = tid >> 5;
    const int warp_m = (wid & 3) * 32, warp_n = (wid >> 2) * 64;
    const int grp = lane >> 2, tg = lane & 3;
    const uint32_t lL = laneL_off(lane), lR = laneR_off(lane);

    const int r  = blockIdx.x >> 1;
    const int o0 = (blockIdx.x & 1) * 128;
    const int m0 = blockIdx.y * 128;

    if (tid < 128) {
        float s = 0.f;
#pragma unroll
        for (int d = 0; d < RELd; d++)
            s += We[r * RELd + d] * W[((size_t)r * (Fdim + RELd) + Fdim + d) * OUTd + o0 + tid];
        sCv[tid] = s;
    }

    const __half* Lb = g_Xh + (size_t)m0 * Fdim;
    const __half* Rb = g_Wh + ((size_t)r * OUTd + o0) * Fdim;

    float acc[2][8][4];
#pragma unroll
    for (int mt = 0; mt < 2; mt++)
#pragma unroll
        for (int nt = 0; nt < 8; nt++)
#pragma unroll
            for (int j = 0; j < 4; j++) acc[mt][nt][j] = 0.f;

    auto loadc = [&](int k0, int s) {
#pragma unroll
        for (int i = 0; i < 4; i++) {
            int f = tid + i * 256;
            int row = f >> 3, seg = f & 7;
            CPA16(slU[s] + row * (LSTR * 2) + seg * 16, Lb + (size_t)row * Fdim + k0 + seg * 8);
            CPA16(srU[s] + row * (LSTR * 2) + seg * 16, Rb + (size_t)row * Fdim + k0 + seg * 8);
        }
    };

    const int NC = Fdim / KC;  // 4
    loadc(0, 0); CPA_COMMIT();

    for (int c = 0; c < NC; c++) {
        const int buf = c & 1;
        CPA_WAIT0();
        __syncthreads();
        if (c + 1 < NC) { loadc((c + 1) * KC, buf ^ 1); CPA_COMMIT(); }

        const uint32_t baseL = slU[buf] + warp_m * (LSTR * 2) + lL;
        const uint32_t baseR = srU[buf] + warp_n * (LSTR * 2) + lR;
#pragma unroll
        for (int j16 = 0; j16 < 4; j16++) {
            const uint32_t kb = j16 * 32;     // 16 halfs
            uint32_t a0[4], a1[4], bb[4][4];
            ldsm4(a0[0], a0[1], a0[2], a0[3], baseL + kb);
            ldsm4(a1[0], a1[1], a1[2], a1[3], baseL + 16 * (LSTR * 2) + kb);
#pragma unroll
            for (int jp = 0; jp < 4; jp++)
                ldsm4(bb[jp][0], bb[jp][1], bb[jp][2], bb[jp][3],
                      baseR + jp * 16 * (LSTR * 2) + kb);
#pragma unroll
            for (int jp = 0; jp < 4; jp++) {
                mma16(acc[0][2 * jp],     a0[0], a0[1], a0[2], a0[3], bb[jp][0], bb[jp][1]);
                mma16(acc[1][2 * jp],     a1[0], a1[1], a1[2], a1[3], bb[jp][0], bb[jp][1]);
                mma16(acc[0][2 * jp + 1], a0[0], a0[1], a0[2], a0[3], bb[jp][2], bb[jp][3]);
                mma16(acc[1][2 * jp + 1], a1[0], a1[1], a1[2], a1[3], bb[jp][2], bb[jp][3]);
            }
        }
    }

    const bool isId = (r == 2 || r == 5 || r == 6);
    if (isId) {
        const int zi = (r == 2) ? 0 : (r == 5) ? 1 : 2;
#pragma unroll
        for (int mt = 0; mt < 2; mt++) {
#pragma unroll
            for (int nt = 0; nt < 8; nt++) {
                const int ol = warp_n + nt * 8 + 2 * tg;
                const float2 cv = *(const float2*)(sCv + ol);
                const int o = o0 + ol;
                int mg = m0 + warp_m + mt * 16 + grp;
                int b = mg >> 10, n = mg & 1023;
                __half* dst = g_H3h + (((size_t)(zi * Bx + b) * Nn + n) * OUTd) + o;
                *(__half2*)dst = __floats2half2_rn(acc[mt][nt][0] + cv.x, acc[mt][nt][1] + cv.y);
                mg += 8; b = mg >> 10; n = mg & 1023;
                dst = g_H3h + (((size_t)(zi * Bx + b) * Nn + n) * OUTd) + o;
                *(__half2*)dst = __floats2half2_rn(acc[mt][nt][2] + cv.x, acc[mt][nt][3] + cv.y);
            }
        }
    } else {
        const int ti = (r < 2) ? r : r - 1;   // 0,1,3,4 -> 0,1,2,3
        __syncthreads();
        __half* sO = smh;                     // 128 rows(o) x OSTR halfs(m)
#pragma unroll
        for (int mt = 0; mt < 2; mt++) {
#pragma unroll
            for (int nt = 0; nt < 8; nt++) {
                const int ol = warp_n + nt * 8 + 2 * tg;
                const float2 cv = *(const float2*)(sCv + ol);
                const int ml = warp_m + mt * 16 + grp;
                sO[ol * OSTR + ml]           = __float2half_rn(acc[mt][nt][0] + cv.x);
                sO[(ol + 1) * OSTR + ml]     = __float2half_rn(acc[mt][nt][1] + cv.y);
                sO[ol * OSTR + ml + 8]       = __float2half_rn(acc[mt][nt][2] + cv.x);
                sO[(ol + 1) * OSTR + ml + 8] = __float2half_rn(acc[mt][nt][3] + cv.y);
            }
        }
        __syncthreads();
        const int b = m0 >> 10, n0l = m0 & 1023;
        __half* Hbase = g_Hth + ((size_t)(ti * Bx + b) * OUTd + o0) * Nn + n0l;
#pragma unroll
        for (int i = 0; i < 8; i++) {
            int f = tid + i * 256;
            int row = f >> 4, seg = f & 15;
            uint4 v = *(const uint4*)(sO + row * OSTR + seg * 8);
            *(uint4*)(Hbase + (size_t)row * Nn + seg * 8) = v;
        }
    }
}

// ---------------------------------------------------------------------------
// Aggregation (fp16, LDSM, unified): Ph[p][b][n][o] = L @ R^T
__global__ __launch_bounds__(256, 2) void agg_pass(const float* __restrict__ A1,
                                                   const float* __restrict__ A2) {
    extern __shared__ __align__(16) __half smh[];
    const uint32_t smU = smem_u32(smh);
    const uint32_t slU[2] = { smU, smU + AGBUF * 2 };
    const uint32_t srU[2] = { smU + 2 * AGBUF * 2, smU + 3 * AGBUF * 2 };

    const int tid = threadIdx.x, lane = tid & 31, wid = tid >> 5;
    const int warp_m = (wid & 3) * 32, warp_n = (wid >> 2) * 64;
    const int grp = lane >> 2, tg = lane & 3;
    const uint32_t lL = laneL_off(lane), lR = laneR_off(lane);

    const int o0 = blockIdx.x * 128;
    const int n0 = blockIdx.y * 128;
    const int z  = blockIdx.z;
    const int b  = z & 7;
    const int p  = z >> 3;
    const int q  = p & 1;

    const __half* Lb = (p < 2 ? (q ? g_A2h : g_A1h) : (q ? g_A2t : g_A1t))
                       + ((size_t)b * Nn + n0) * Nn;
    const __half* Rb = g_Hth + ((size_t)(p * Bx + b) * OUTd + o0) * Nn;
    __half* Pout = g_Ph + (size_t)p * PSTR + (size_t)b * Nn * OUTd;

    float acc[2][8][4];
#pragma unroll
    for (int mt = 0; mt < 2; mt++)
#pragma unroll
        for (int nt = 0; nt < 8; nt++)
#pragma unroll
            for (int j = 0; j < 4; j++) acc[mt][nt][j] = 0.f;

    auto loadc = [&](int k0, int s) {
#pragma unroll
        for (int i = 0; i < 4; i++) {
            int f = tid + i * 256;
            int row = f >> 3, seg = f & 7;
            CPA16(slU[s] + row * (LSTR * 2) + seg * 16, Lb + (size_t)row * Nn + k0 + seg * 8);
            CPA16(srU[s] + row * (LSTR * 2) + seg * 16, Rb + (size_t)row * Nn + k0 + seg * 8);
        }
    };

    const int NC = Nn / KC;  // 16
    loadc(0, 0); CPA_COMMIT();

    for (int c = 0; c < NC; c++) {
        const int buf = c & 1;
        CPA_WAIT0();
        __syncthreads();
        if (c + 1 < NC) { loadc((c + 1) * KC, buf ^ 1); CPA_COMMIT(); }

        const uint32_t baseL = slU[buf] + warp_m * (LSTR * 2) + lL;
        const uint32_t baseR = srU[buf] + warp_n * (LSTR * 2) + lR;
#pragma unroll
        for (int j16 = 0; j16 < 4; j16++) {
            const uint32_t kb = j16 * 32;
            uint32_t a0[4], a1[4], bb[4][4];
            ldsm4(a0[0], a0[1], a0[2], a0[3], baseL + kb);
            ldsm4(a1[0], a1[1], a1[2], a1[3], baseL + 16 * (LSTR * 2) + kb);
#pragma unroll
            for (int jp = 0; jp < 4; jp++)
                ldsm4(bb[jp][0], bb[jp][1], bb[jp][2], bb[jp][3],
                      baseR + jp * 16 * (LSTR * 2) + kb);
#pragma unroll
            for (int jp = 0; jp < 4; jp++) {
                mma16(acc[0][2 * jp],     a0[0], a0[1], a0[2], a0[3], bb[jp][0], bb[jp][1]);
                mma16(acc[1][2 * jp],     a1[0], a1[1], a1[2], a1[3], bb[jp][0], bb[jp][1]);
                mma16(acc[0][2 * jp + 1], a0[0], a0[1], a0[2], a0[3], bb[jp][2], bb[jp][3]);
                mma16(acc[1][2 * jp + 1], a1[0], a1[1], a1[2], a1[3], bb[jp][2], bb[jp][3]);
            }
        }
    }

#pragma unroll
    for (int mt = 0; mt < 2; mt++) {
#pragma unroll
        for (int nt = 0; nt < 8; nt++) {
            const int o = o0 + warp_n + nt * 8 + 2 * tg;
#pragma unroll
            for (int h = 0; h < 2; h++) {
                const int n = n0 + warp_m + mt * 16 + grp + h * 8;
                *(__half2*)(Pout + (size_t)n * OUTd + o) =
                    __floats2half2_rn(acc[mt][nt][2 * h], acc[mt][nt][2 * h + 1]);
            }
        }
    }
}

// ---------------------------------------------------------------------------
// out = float( max(Ph0..3, H3h0..2) ) + bias
__global__ __launch_bounds__(256) void fold_kernel(const float* __restrict__ bias,
                                                   float* __restrict__ out) {
    const int idx = (blockIdx.x * 256 + threadIdx.x) * 8;
    uint4 u = *(const uint4*)(g_Ph + idx);
    __half2* hv = (__half2*)&u;
#pragma unroll
    for (int p = 1; p < 4; p++) {
        uint4 t = *(const uint4*)(g_Ph + (size_t)p * PSTR + idx);
        __half2* ht = (__half2*)&t;
#pragma unroll
        for (int j = 0; j < 4; j++) hv[j] = __hmax2(hv[j], ht[j]);
    }
#pragma unroll
    for (int zi = 0; zi < 3; zi++) {
        uint4 t = *(const uint4*)(g_H3h + (size_t)zi * PSTR + idx);
        __half2* ht = (__half2*)&t;
#pragma unroll
        for (int j = 0; j < 4; j++) hv[j] = __hmax2(hv[j], ht[j]);
    }
    const int bi = idx & (Nn * OUTd - 1);
    float4 b0 = *(const float4*)(bias + bi);
    float4 b1 = *(const float4*)(bias + bi + 4);
    float2 f0 = __half22float2(hv[0]), f1 = __half22float2(hv[1]);
    float2 f2 = __half22float2(hv[2]), f3 = __half22float2(hv[3]);
    float4 o0 = make_float4(f0.x + b0.x, f0.y + b0.y, f1.x + b0.z, f1.y + b0.w);
    float4 o1 = make_float4(f2.x + b1.x, f2.y + b1.y, f3.x + b1.z, f3.y + b1.w);
    *(float4*)(out + idx)     = o0;
    *(float4*)(out + idx + 4) = o1;
}

// ---------------------------------------------------------------------------
extern "C" void kernel_launch(void* const* d_in, const int* in_sizes, int n_in,
                              void* d_out, int out_size) {
    const float* X    = (const float*)d_in[0];
    const float* A1   = (const float*)d_in[1];
    const float* A2   = (const float*)d_in[2];
    const float* W    = (const float*)d_in[3];
    const float* We   = (const float*)d_in[4];
    const float* bias = (const float*)d_in[5];
    float* out = (float*)d_out;

    static cudaStream_t s2 = nullptr;
    static cudaEvent_t evFork = nullptr, evJoin = nullptr;
    if (s2 == nullptr) {
        cudaStreamCreateWithFlags(&s2, cudaStreamNonBlocking);
        cudaEventCreateWithFlags(&evFork, cudaEventDisableTiming);
        cudaEventCreateWithFlags(&evJoin, cudaEventDisableTiming);
        cudaFuncSetAttribute(hw_mma,   cudaFuncAttributeMaxDynamicSharedMemorySize, AG_SMEM_BYTES);
        cudaFuncSetAttribute(agg_pass, cudaFuncAttributeMaxDynamicSharedMemorySize, AG_SMEM_BYTES);
    }

    cudaEventRecord(evFork, 0);
    cudaStreamWaitEvent(s2, evFork, 0);
    ah_kernel<<<dim3(16, 16, 16), 256, 0, s2>>>(A1, A2);
    cudaEventRecord(evJoin, s2);

    xh_kernel<<<2048, 256>>>(X);
    wh_prep<<<448, 256>>>(W);

    dim3 gHW(14, 64);
    hw_mma<<<gHW, 256, AG_SMEM_BYTES>>>(W, We);

    cudaStreamWaitEvent(0, evJoin, 0);

    dim3 gAgg(2, 8, 32);
    agg_pass<<<gAgg, 256, AG_SMEM_BYTES>>>(A1, A2);

    fold_kernel<<<(Bx * Nn * OUTd) / 2048, 256>>>(bias, out);
}